// round 4
// baseline (speedup 1.0000x reference)
#include <cuda_runtime.h>
#include <cuda_bf16.h>
#include <cstdint>
#include <cstddef>

// Seq2seq GRU encoder/decoder, fp32 persistent-decoder implementation.
// B=4096, F=128, H=256, ISEQ=96, PSEQ=48.
//
//   prep_kernel    : transpose weights into k-major, gate-triplet-interleaved scratch
//   seq2seq_kernel : persistent, 128 CTAs x 32 batch rows:
//                      encoder GRU cell on x_last (h0=0)  -> h_enc (SMEM)
//                      fc + relu                          -> h (SMEM, [m][c])
//                      48 decoder GRU steps, h never leaves SMEM

#define BATCH   4096
#define F_      128
#define H_      256
#define ISEQ    96
#define PSEQ    48
#define MTILE   32
#define XST     36      // k-major smem row stride (floats), multiple of 4 for float4
#define HS2ST   132     // h row-major stride (floats)
#define BUFSZ   6144    // floats per weight-chunk buffer (16 x 384)

// ---------------- device scratch (allocation-free rule) ----------------
__device__ float g_WencT[128 * 768];   // [k][3c+g] of W_ih_enc
__device__ float g_WihT [128 * 384];   // [k][3c+g] of W_ih_dec
__device__ float g_WhhT [128 * 384];   // [k][3c+g] of W_hh_dec
__device__ float g_WfcT [256 * 128];   // [k][c]    of W_fc

// ---------------- helpers ----------------
__device__ __forceinline__ float sigf(float x) { return 1.0f / (1.0f + __expf(-x)); }

__device__ __forceinline__ void cp_async16(float* sdst, const float* gsrc) {
    unsigned sa = (unsigned)__cvta_generic_to_shared(sdst);
    asm volatile("cp.async.cg.shared.global [%0], [%1], 16;" :: "r"(sa), "l"(gsrc));
}
__device__ __forceinline__ void cp_commit() { asm volatile("cp.async.commit_group;"); }
__device__ __forceinline__ void cp_wait1()  { asm volatile("cp.async.wait_group 1;"); }
__device__ __forceinline__ void cp_wait0()  { asm volatile("cp.async.wait_group 0;"); }

// ---------------- prep: weight re-layout ----------------
__global__ void prep_kernel(const float* __restrict__ Wihe,
                            const float* __restrict__ Wihd,
                            const float* __restrict__ Whhd,
                            const float* __restrict__ Wfc) {
    int idx = blockIdx.x * 256 + threadIdx.x;
    if (idx < 98304) {                       // 128 x 768 encoder ih
        int k = idx / 768, s = idx - k * 768;
        int c = s / 3, g = s - 3 * c;
        g_WencT[idx] = Wihe[(g * 256 + c) * 128 + k];
    } else if (idx < 147456) {               // 128 x 384 decoder ih
        int j = idx - 98304;
        int k = j / 384, s = j - k * 384;
        int c = s / 3, g = s - 3 * c;
        g_WihT[j] = Wihd[(g * 128 + c) * 128 + k];
    } else if (idx < 196608) {               // 128 x 384 decoder hh
        int j = idx - 147456;
        int k = j / 384, s = j - k * 384;
        int c = s / 3, g = s - 3 * c;
        g_WhhT[j] = Whhd[(g * 128 + c) * 128 + k];
    } else if (idx < 229376) {               // 256 x 128 fc
        int j = idx - 196608;
        int k = j / 128, c = j - k * 128;
        g_WfcT[j] = Wfc[c * 256 + k];
    }
}

// ---------------- chunk loaders (gmem -> smem, cp.async) ----------------
// 16 x 384 chunk. 256 threads: row = tid>>4, 24 floats each.
__device__ __forceinline__ void load_chunk384(float* dst, const float* src,
                                              int srcStride, int tid) {
    int row = tid >> 4;
    int col = (tid & 15) * 24;
    const float* s = src + (size_t)row * srcStride + col;
    float* d = dst + row * 384 + col;
#pragma unroll
    for (int i = 0; i < 6; i++) cp_async16(d + i * 4, s + i * 4);
}
// 16 x 128 chunk (fc weights).
__device__ __forceinline__ void load_chunk128(float* dst, const float* src, int tid) {
    int row = tid >> 4;
    int col = (tid & 15) * 8;
    const float* s = src + row * 128 + col;
    float* d = dst + row * 128 + col;
    cp_async16(d, s);
    cp_async16(d + 4, s + 4);
}

// Load a [32 x 128] x tile and transpose into xs[k][m] (stride XST).
// Warp = one 16-float f chunk, lanes = batch rows -> conflict-free STS.
__device__ __forceinline__ void load_x_tile(const float* rowbase, int rowStride,
                                            float* xs, int b0, int tid) {
    int m  = tid & 31;
    int f0 = (tid >> 5) * 16;
    const float4* s = (const float4*)(rowbase + (size_t)(b0 + m) * rowStride + f0);
    float4 v0 = s[0], v1 = s[1], v2 = s[2], v3 = s[3];
    float vv[16] = {v0.x, v0.y, v0.z, v0.w, v1.x, v1.y, v1.z, v1.w,
                    v2.x, v2.y, v2.z, v2.w, v3.x, v3.y, v3.z, v3.w};
#pragma unroll
    for (int i = 0; i < 16; i++) xs[(f0 + i) * XST + m] = vv[i];
}

// ---------------- GEMM micro-tiles ----------------
// Thread (tx,ty): rows 4*ty..+3, storage cols 12*tx..+11 (4 gate triplets).
// A k-major [k][m] (stride XST): broadcast float4 reads.
__device__ __forceinline__ void gemm_x_full(const float* __restrict__ A,
                                            const float* __restrict__ Bt,
                                            int tx, int ty, float (&acc)[4][12]) {
#pragma unroll
    for (int k = 0; k < 16; k++) {
        float4 av = *(const float4*)(A + k * XST + 4 * ty);
        const float* bp = Bt + k * 384 + 12 * tx;
        float4 b0 = *(const float4*)(bp);
        float4 b1 = *(const float4*)(bp + 4);
        float4 b2 = *(const float4*)(bp + 8);
        float aa[4]  = {av.x, av.y, av.z, av.w};
        float bb[12] = {b0.x, b0.y, b0.z, b0.w, b1.x, b1.y, b1.z, b1.w,
                        b2.x, b2.y, b2.z, b2.w};
#pragma unroll
        for (int r = 0; r < 4; r++)
#pragma unroll
            for (int j = 0; j < 12; j++)
                acc[r][j] = fmaf(aa[r], bb[j], acc[r][j]);
    }
}

// A from h stored row-major [m][HS2ST]: scalar broadcast reads.
__device__ __forceinline__ void gemm_h_full(const float* __restrict__ hs2, int k0,
                                            const float* __restrict__ Bt,
                                            int tx, int ty, float (&acc)[4][12]) {
#pragma unroll
    for (int k = 0; k < 16; k++) {
        const float* bp = Bt + k * 384 + 12 * tx;
        float4 b0 = *(const float4*)(bp);
        float4 b1 = *(const float4*)(bp + 4);
        float4 b2 = *(const float4*)(bp + 8);
        float bb[12] = {b0.x, b0.y, b0.z, b0.w, b1.x, b1.y, b1.z, b1.w,
                        b2.x, b2.y, b2.z, b2.w};
        float aa[4];
#pragma unroll
        for (int r = 0; r < 4; r++) aa[r] = hs2[(4 * ty + r) * HS2ST + k0 + k];
#pragma unroll
        for (int r = 0; r < 4; r++)
#pragma unroll
            for (int j = 0; j < 12; j++)
                acc[r][j] = fmaf(aa[r], bb[j], acc[r][j]);
    }
}

// Same, but n-gate columns (j%3==2) go to a separate accumulator (for r*h_n).
__device__ __forceinline__ void gemm_h_split(const float* __restrict__ hs2, int k0,
                                             const float* __restrict__ Bt,
                                             int tx, int ty,
                                             float (&acc)[4][12], float (&accn)[4][4]) {
#pragma unroll
    for (int k = 0; k < 16; k++) {
        const float* bp = Bt + k * 384 + 12 * tx;
        float4 b0 = *(const float4*)(bp);
        float4 b1 = *(const float4*)(bp + 4);
        float4 b2 = *(const float4*)(bp + 8);
        float bb[12] = {b0.x, b0.y, b0.z, b0.w, b1.x, b1.y, b1.z, b1.w,
                        b2.x, b2.y, b2.z, b2.w};
        float aa[4];
#pragma unroll
        for (int r = 0; r < 4; r++) aa[r] = hs2[(4 * ty + r) * HS2ST + k0 + k];
#pragma unroll
        for (int r = 0; r < 4; r++)
#pragma unroll
            for (int j = 0; j < 12; j++) {
                if (j % 3 == 2) accn[r][j / 3] = fmaf(aa[r], bb[j], accn[r][j / 3]);
                else            acc[r][j]      = fmaf(aa[r], bb[j], acc[r][j]);
            }
    }
}

// fc GEMM: out 32x128, k chunked by 16. Thread tile 4x4 (cols 4*tx..+3).
__device__ __forceinline__ void gemm_fc(const float* __restrict__ A,
                                        const float* __restrict__ Bt,
                                        int tx, int ty, float (&acc)[4][4]) {
#pragma unroll
    for (int k = 0; k < 16; k++) {
        float4 av = *(const float4*)(A + k * XST + 4 * ty);
        float4 bv = *(const float4*)(Bt + k * 128 + 4 * tx);
        float aa[4] = {av.x, av.y, av.z, av.w};
        float bb[4] = {bv.x, bv.y, bv.z, bv.w};
#pragma unroll
        for (int r = 0; r < 4; r++)
#pragma unroll
            for (int j = 0; j < 4; j++)
                acc[r][j] = fmaf(aa[r], bb[j], acc[r][j]);
    }
}

// ---------------- main persistent kernel ----------------
__global__ void __launch_bounds__(256, 1)
seq2seq_kernel(const float* __restrict__ z_in,
               const float* __restrict__ z_tar,
               const float* __restrict__ bihe,
               const float* __restrict__ bhhe,
               const float* __restrict__ bfc,
               const float* __restrict__ bihd,
               const float* __restrict__ bhhd,
               const int*   __restrict__ tf_ptr,
               float*       __restrict__ out) {
    extern __shared__ float sm[];
    float* Bs  = sm;                       // 2 x 6144 weight chunk buffers
    float* xs  = sm + 2 * BUFSZ;           // 128 x XST   x tile, k-major
    float* hs2 = xs + 128 * XST;           // 32 x HS2ST  h, row-major [m][c]
    float* he  = hs2 + MTILE * HS2ST;      // 256 x XST   h_enc, k-major

    const int tid = threadIdx.x;
    const int tx = tid & 31, ty = tid >> 5;
    const int b0 = blockIdx.x * MTILE;
    const bool tf = (*tf_ptr != 0);

    // ======== encoder: GRU(x_last, h0=0) -> he ========
    load_x_tile(z_in + (size_t)(ISEQ - 1) * F_, ISEQ * F_, xs, b0, tid);

#pragma unroll 1
    for (int cc = 0; cc < 2; cc++) {
        float acc[4][12];
#pragma unroll
        for (int r = 0; r < 4; r++)
#pragma unroll
            for (int j = 0; j < 12; j++) acc[r][j] = 0.0f;

        load_chunk384(Bs, g_WencT + cc * 384, 768, tid);
        cp_commit();
#pragma unroll 1
        for (int ch = 0; ch < 8; ch++) {
            if (ch < 7) {
                load_chunk384(Bs + ((ch + 1) & 1) * BUFSZ,
                              g_WencT + (size_t)(ch + 1) * 16 * 768 + cc * 384, 768, tid);
                cp_commit();
                cp_wait1();
            } else {
                cp_wait0();
            }
            __syncthreads();
            gemm_x_full(xs + ch * 16 * XST, Bs + (ch & 1) * BUFSZ, tx, ty, acc);
            __syncthreads();
        }
        // combine (gh = b_hh since h0 = 0): h_enc = (1-z)*n
#pragma unroll
        for (int cj = 0; cj < 4; cj++) {
            int c = cc * 128 + 4 * tx + cj;
            float br  = bihe[c] + bhhe[c];
            float bz  = bihe[H_ + c] + bhhe[H_ + c];
            float bni = bihe[2 * H_ + c];
            float bnh = bhhe[2 * H_ + c];
#pragma unroll
            for (int r = 0; r < 4; r++) {
                float rr = sigf(acc[r][3 * cj] + br);
                float zz = sigf(acc[r][3 * cj + 1] + bz);
                float nn = tanhf(acc[r][3 * cj + 2] + bni + rr * bnh);
                he[c * XST + 4 * ty + r] = (1.0f - zz) * nn;
            }
        }
    }

    // ======== fc + relu -> hs2 (dec_h0, row-major) ========
    {
        float acc2[4][4];
#pragma unroll
        for (int r = 0; r < 4; r++)
#pragma unroll
            for (int j = 0; j < 4; j++) acc2[r][j] = 0.0f;

        load_chunk128(Bs, g_WfcT, tid);
        cp_commit();
#pragma unroll 1
        for (int ch = 0; ch < 16; ch++) {
            if (ch < 15) {
                load_chunk128(Bs + ((ch + 1) & 1) * BUFSZ, g_WfcT + (ch + 1) * 16 * 128, tid);
                cp_commit();
                cp_wait1();
            } else {
                cp_wait0();
            }
            __syncthreads();
            gemm_fc(he + ch * 16 * XST, Bs + (ch & 1) * BUFSZ, tx, ty, acc2);
            __syncthreads();
        }
#pragma unroll
        for (int r = 0; r < 4; r++) {
            float h0 = fmaxf(acc2[r][0] + bfc[4 * tx + 0], 0.0f);
            float h1 = fmaxf(acc2[r][1] + bfc[4 * tx + 1], 0.0f);
            float h2 = fmaxf(acc2[r][2] + bfc[4 * tx + 2], 0.0f);
            float h3 = fmaxf(acc2[r][3] + bfc[4 * tx + 3], 0.0f);
            *(float4*)(hs2 + (4 * ty + r) * HS2ST + 4 * tx) = make_float4(h0, h1, h2, h3);
        }
    }

    // ======== decoder: 48 GRU steps, h resident in SMEM ========
    float br_[4], bz_[4], bni_[4], bnh_[4];
#pragma unroll
    for (int cj = 0; cj < 4; cj++) {
        int c = 4 * tx + cj;
        br_[cj]  = bihd[c] + bhhd[c];
        bz_[cj]  = bihd[F_ + c] + bhhd[F_ + c];
        bni_[cj] = bihd[2 * F_ + c];
        bnh_[cj] = bhhd[2 * F_ + c];
    }

#pragma unroll 1
    for (int t = 0; t < PSEQ; t++) {
        // x_0 = x_last (already in xs). TF: x_t = z_tar[:,t-1,:]. Non-TF: x_t = h_{t-1}.
        if (t > 0 && tf)
            load_x_tile(z_tar + (size_t)(t - 1) * F_, PSEQ * F_, xs, b0, tid);
        const bool gi_x = (t == 0) || tf;

        float acc[4][12];
        float accn[4][4];
#pragma unroll
        for (int r = 0; r < 4; r++) {
#pragma unroll
            for (int j = 0; j < 12; j++) acc[r][j] = 0.0f;
#pragma unroll
            for (int j = 0; j < 4; j++)  accn[r][j] = 0.0f;
        }

        // 16 weight chunks: 0..7 = W_ih (gi), 8..15 = W_hh (gh), double-buffered.
        load_chunk384(Bs, g_WihT, 384, tid);
        cp_commit();
#pragma unroll 1
        for (int ch = 0; ch < 16; ch++) {
            if (ch < 15) {
                const float* src = (ch + 1 < 8)
                    ? g_WihT + (size_t)(ch + 1) * 16 * 384
                    : g_WhhT + (size_t)(ch + 1 - 8) * 16 * 384;
                load_chunk384(Bs + ((ch + 1) & 1) * BUFSZ, src, 384, tid);
                cp_commit();
                cp_wait1();
            } else {
                cp_wait0();
            }
            __syncthreads();
            const float* Bt = Bs + (ch & 1) * BUFSZ;
            if (ch < 8) {
                if (gi_x) gemm_x_full(xs + ch * 16 * XST, Bt, tx, ty, acc);
                else      gemm_h_full(hs2, ch * 16, Bt, tx, ty, acc);
            } else {
                gemm_h_split(hs2, (ch - 8) * 16, Bt, tx, ty, acc, accn);
            }
            __syncthreads();
        }

        // GRU combine; write h to out and back into hs2 (exclusive per thread).
#pragma unroll
        for (int r = 0; r < 4; r++) {
            float4 hp = *(const float4*)(hs2 + (4 * ty + r) * HS2ST + 4 * tx);
            float hprev[4] = {hp.x, hp.y, hp.z, hp.w};
            float hn[4];
#pragma unroll
            for (int cj = 0; cj < 4; cj++) {
                float rr = sigf(acc[r][3 * cj] + br_[cj]);
                float zz = sigf(acc[r][3 * cj + 1] + bz_[cj]);
                float nn = tanhf(acc[r][3 * cj + 2] + bni_[cj]
                                 + rr * (accn[r][cj] + bnh_[cj]));
                hn[cj] = (1.0f - zz) * nn + zz * hprev[cj];
            }
            float4 o = make_float4(hn[0], hn[1], hn[2], hn[3]);
            *(float4*)(out + ((size_t)(b0 + 4 * ty + r) * PSEQ + t) * F_ + 4 * tx) = o;
            *(float4*)(hs2 + (4 * ty + r) * HS2ST + 4 * tx) = o;
        }
        // next iteration's first in-loop __syncthreads orders these hs2 writes
        // before any cross-thread gemm_h reads.
    }
}

// ---------------- launch ----------------
extern "C" void kernel_launch(void* const* d_in, const int* in_sizes, int n_in,
                              void* d_out, int out_size) {
    const float* z_in  = (const float*)d_in[0];
    const float* z_tar = (const float*)d_in[1];
    const float* Wihe  = (const float*)d_in[2];
    // d_in[3] = W_hh_enc: unused (encoder h0 = 0)
    const float* bihe  = (const float*)d_in[4];
    const float* bhhe  = (const float*)d_in[5];
    const float* Wfc   = (const float*)d_in[6];
    const float* bfc   = (const float*)d_in[7];
    const float* Wihd  = (const float*)d_in[8];
    const float* Whhd  = (const float*)d_in[9];
    const float* bihd  = (const float*)d_in[10];
    const float* bhhd  = (const float*)d_in[11];
    const int*   tf    = (const int*)d_in[12];
    float* out = (float*)d_out;

    prep_kernel<<<896, 256>>>(Wihe, Wihd, Whhd, Wfc);

    const int SMEM = (2 * BUFSZ + 128 * XST + MTILE * HS2ST + 256 * XST) * 4;  // 121344 B
    cudaFuncSetAttribute(seq2seq_kernel, cudaFuncAttributeMaxDynamicSharedMemorySize, SMEM);
    seq2seq_kernel<<<128, 256, SMEM>>>(z_in, z_tar, bihe, bhhe, bfc,
                                       bihd, bhhd, tf, out);
}

// round 7
// speedup vs baseline: 2.5151x; 2.5151x over previous
#include <cuda_runtime.h>
#include <cuda_bf16.h>
#include <cstdint>
#include <cstddef>

#define BATCH 4096
#define F_ 128
#define H_ 256
#define ISEQ 96
#define PSEQ 48
#define XST 36
// dec SMEM byte offsets
#define SRES 0
#define SXHI 147456
#define SXLO 164864
#define SHHI 182272
#define SHLO 199680
#define SMDEC 217088

__device__ float g_WencT[128 * 768];
__device__ float g_WfcT [256 * 128];
__device__ float g_h0   [BATCH * F_];
__device__ __align__(128) unsigned char g_Bres[2][147456]; // Wih_hi|Whh_hi|Whh_lo per half
__device__ __align__(128) unsigned char g_B0lo[2][49152];  // Wih_lo, fragment layout

__device__ __forceinline__ float sigf(float x) { return 1.0f / (1.0f + __expf(-x)); }
__device__ __forceinline__ void cp_async16(void* sdst, const void* gsrc) {
    unsigned sa = (unsigned)__cvta_generic_to_shared(sdst);
    asm volatile("cp.async.cg.shared.global [%0], [%1], 16;" :: "r"(sa), "l"(gsrc));
}
__device__ __forceinline__ void cp_commit() { asm volatile("cp.async.commit_group;"); }
__device__ __forceinline__ void cp_wait1()  { asm volatile("cp.async.wait_group 1;"); }
__device__ __forceinline__ void cp_wait0()  { asm volatile("cp.async.wait_group 0;"); }
__device__ __forceinline__ uint32_t lds32(uint32_t a) {
    uint32_t v; asm volatile("ld.shared.b32 %0, [%1];" : "=r"(v) : "r"(a)); return v;
}
__device__ __forceinline__ void mma16816(float* c, const uint32_t* a, const uint32_t* b) {
    asm volatile("mma.sync.aligned.m16n8k16.row.col.f32.bf16.bf16.f32 "
                 "{%0,%1,%2,%3},{%4,%5,%6,%7},{%8,%9},{%0,%1,%2,%3};"
                 : "+f"(c[0]), "+f"(c[1]), "+f"(c[2]), "+f"(c[3])
                 : "r"(a[0]), "r"(a[1]), "r"(a[2]), "r"(a[3]), "r"(b[0]), "r"(b[1]));
}
__device__ __forceinline__ uint32_t mapa_u32(uint32_t a, uint32_t r) {
    uint32_t o; asm volatile("mapa.shared::cluster.u32 %0, %1, %2;" : "=r"(o) : "r"(a), "r"(r));
    return o;
}
__device__ __forceinline__ void stc32(uint32_t a, uint32_t v) {
    asm volatile("st.shared::cluster.u32 [%0], %1;" :: "r"(a), "r"(v) : "memory");
}
#define CSYNC() do { asm volatile("barrier.cluster.arrive.aligned;" ::: "memory"); \
                     asm volatile("barrier.cluster.wait.aligned;" ::: "memory"); } while (0)
__device__ __forceinline__ uint32_t pk2(__nv_bfloat16 a, __nv_bfloat16 b) {
    return (uint32_t)__bfloat16_as_ushort(a) | ((uint32_t)__bfloat16_as_ushort(b) << 16);
}

// ---------------- prep ----------------
__global__ void prep_kernel(const float* __restrict__ Wihe, const float* __restrict__ Wfc,
                            const float* __restrict__ Wihd, const float* __restrict__ Whhd) {
    int idx = blockIdx.x * 256 + threadIdx.x;
    if (idx < 98304) {
        int k = idx / 768, s = idx - k * 768, c = s / 3, g = s - 3 * c;
        g_WencT[idx] = Wihe[(g * 256 + c) * 128 + k];
    } else if (idx < 131072) {
        int j = idx - 98304, k = j / 128, c = j - k * 128;
        g_WfcT[j] = Wfc[c * 256 + k];
    } else if (idx < 229376) {
        int j = idx - 131072;
        int half = j / 49152, r2 = j % 49152, gm = r2 / 24576, e = r2 % 24576;
        int col = e >> 7, k = e & 127;
        int gate = col >> 6, ch = half * 64 + (col & 63);
        const float* W = gm ? Whhd : Wihd;
        float w = W[(size_t)(gate * 128 + ch) * 128 + k];
        __nv_bfloat16 hi = __float2bfloat16(w);
        __nv_bfloat16 lo = __float2bfloat16(w - __bfloat162float(hi));
        int kt = k >> 4, kk = k & 15;
        uint32_t sb = (uint32_t)(kt * 6144 + col * 32) + (uint32_t)((kk * 2) ^ ((col & 4) << 2));
        uint32_t pb = (uint32_t)(kt * 6144 + col * 32 + kk * 2);
        if (!gm) {
            *(__nv_bfloat16*)(g_Bres[half] + sb) = hi;
            *(__nv_bfloat16*)(g_B0lo[half] + pb) = lo;
        } else {
            *(__nv_bfloat16*)(g_Bres[half] + 49152 + sb) = hi;
            *(__nv_bfloat16*)(g_Bres[half] + 98304 + sb) = lo;
        }
    }
}

// ---------------- encoder (fp32, proven) ----------------
__device__ __forceinline__ void load_chunk384(float* dst, const float* src, int stride, int tid) {
    int row = tid >> 4, col = (tid & 15) * 24;
    const float* s = src + (size_t)row * stride + col;
    float* d = dst + row * 384 + col;
#pragma unroll
    for (int i = 0; i < 6; i++) cp_async16(d + i * 4, s + i * 4);
}
__device__ __forceinline__ void load_chunk128(float* dst, const float* src, int tid) {
    int row = tid >> 4, col = (tid & 15) * 8;
    cp_async16(dst + row * 128 + col, src + row * 128 + col);
    cp_async16(dst + row * 128 + col + 4, src + row * 128 + col + 4);
}
__device__ __forceinline__ void gemm_x_full(const float* A, const float* Bt,
                                            int tx, int ty, float (&acc)[4][12]) {
#pragma unroll
    for (int k = 0; k < 16; k++) {
        float4 av = *(const float4*)(A + k * XST + 4 * ty);
        const float* bp = Bt + k * 384 + 12 * tx;
        float4 b0 = *(const float4*)bp, b1 = *(const float4*)(bp + 4), b2 = *(const float4*)(bp + 8);
        float aa[4] = {av.x, av.y, av.z, av.w};
        float bb[12] = {b0.x,b0.y,b0.z,b0.w,b1.x,b1.y,b1.z,b1.w,b2.x,b2.y,b2.z,b2.w};
#pragma unroll
        for (int r = 0; r < 4; r++)
#pragma unroll
            for (int j = 0; j < 12; j++) acc[r][j] = fmaf(aa[r], bb[j], acc[r][j]);
    }
}
__device__ __forceinline__ void gemm_fc(const float* A, const float* Bt,
                                        int tx, int ty, float (&acc)[4][4]) {
#pragma unroll
    for (int k = 0; k < 16; k++) {
        float4 av = *(const float4*)(A + k * XST + 4 * ty);
        float4 bv = *(const float4*)(Bt + k * 128 + 4 * tx);
        float aa[4] = {av.x, av.y, av.z, av.w};
        float bb[4] = {bv.x, bv.y, bv.z, bv.w};
#pragma unroll
        for (int r = 0; r < 4; r++)
#pragma unroll
            for (int j = 0; j < 4; j++) acc[r][j] = fmaf(aa[r], bb[j], acc[r][j]);
    }
}

__global__ void __launch_bounds__(256, 1)
enc_kernel(const float* __restrict__ z_in, const float* __restrict__ bihe,
           const float* __restrict__ bhhe, const float* __restrict__ bfc) {
    extern __shared__ float sm[];
    float* Bs = sm;
    float* xs = sm + 12288;
    float* he = xs + 128 * XST;
    const int tid = threadIdx.x, tx = tid & 31, ty = tid >> 5;
    const int b0 = blockIdx.x * 32;
    {
        int m = tid & 31, f0 = (tid >> 5) * 16;
        const float4* s = (const float4*)(z_in + ((size_t)(b0 + m) * ISEQ + ISEQ - 1) * F_ + f0);
        float4 v0 = s[0], v1 = s[1], v2 = s[2], v3 = s[3];
        float vv[16] = {v0.x,v0.y,v0.z,v0.w,v1.x,v1.y,v1.z,v1.w,v2.x,v2.y,v2.z,v2.w,v3.x,v3.y,v3.z,v3.w};
#pragma unroll
        for (int i = 0; i < 16; i++) xs[(f0 + i) * XST + m] = vv[i];
    }
    __syncthreads();
#pragma unroll 1
    for (int cc = 0; cc < 2; cc++) {
        float acc[4][12];
#pragma unroll
        for (int r = 0; r < 4; r++)
#pragma unroll
            for (int j = 0; j < 12; j++) acc[r][j] = 0.0f;
        load_chunk384(Bs, g_WencT + cc * 384, 768, tid);
        cp_commit();
#pragma unroll 1
        for (int ch = 0; ch < 8; ch++) {
            if (ch < 7) {
                load_chunk384(Bs + ((ch + 1) & 1) * 6144,
                              g_WencT + (size_t)(ch + 1) * 16 * 768 + cc * 384, 768, tid);
                cp_commit(); cp_wait1();
            } else cp_wait0();
            __syncthreads();
            gemm_x_full(xs + ch * 16 * XST, Bs + (ch & 1) * 6144, tx, ty, acc);
            __syncthreads();
        }
#pragma unroll
        for (int cj = 0; cj < 4; cj++) {
            int c = cc * 128 + 4 * tx + cj;
            float br = bihe[c] + bhhe[c];
            float bz = bihe[H_ + c] + bhhe[H_ + c];
            float bni = bihe[2 * H_ + c], bnh = bhhe[2 * H_ + c];
#pragma unroll
            for (int r = 0; r < 4; r++) {
                float rr = sigf(acc[r][3 * cj] + br);
                float zz = sigf(acc[r][3 * cj + 1] + bz);
                float nn = tanhf(acc[r][3 * cj + 2] + bni + rr * bnh);
                he[c * XST + 4 * ty + r] = (1.0f - zz) * nn;
            }
        }
    }
    {
        float a2[4][4];
#pragma unroll
        for (int r = 0; r < 4; r++)
#pragma unroll
            for (int j = 0; j < 4; j++) a2[r][j] = 0.0f;
        load_chunk128(Bs, g_WfcT, tid);
        cp_commit();
#pragma unroll 1
        for (int ch = 0; ch < 16; ch++) {
            if (ch < 15) {
                load_chunk128(Bs + ((ch + 1) & 1) * 6144, g_WfcT + (ch + 1) * 16 * 128, tid);
                cp_commit(); cp_wait1();
            } else cp_wait0();
            __syncthreads();
            gemm_fc(he + ch * 16 * XST, Bs + (ch & 1) * 6144, tx, ty, a2);
            __syncthreads();
        }
#pragma unroll
        for (int r = 0; r < 4; r++) {
            float4 o = make_float4(fmaxf(a2[r][0] + bfc[4 * tx + 0], 0.0f),
                                   fmaxf(a2[r][1] + bfc[4 * tx + 1], 0.0f),
                                   fmaxf(a2[r][2] + bfc[4 * tx + 2], 0.0f),
                                   fmaxf(a2[r][3] + bfc[4 * tx + 3], 0.0f));
            *(float4*)(g_h0 + (size_t)(b0 + 4 * ty + r) * 128 + 4 * tx) = o;
        }
    }
}

// ---------------- decoder: pair-split mma.sync with DSMEM h exchange ----------------
// act tile: 64 rows x 128 ch bf16, row stride 136 (272B); hi and lo tiles.
__device__ __forceinline__ void load_act(const float* src, size_t rowStride,
                                         unsigned char* smp, int HIo, int LOo, int tid) {
    int m = tid >> 2, f0 = (tid & 3) * 32;
    const float4* s = (const float4*)(src + (size_t)m * rowStride + f0);
#pragma unroll
    for (int i = 0; i < 8; i++) {
        float4 v = s[i];
        __nv_bfloat16 hx = __float2bfloat16(v.x), hy = __float2bfloat16(v.y);
        __nv_bfloat16 hz = __float2bfloat16(v.z), hw = __float2bfloat16(v.w);
        int byte = m * 272 + (f0 + 4 * i) * 2;
        *(uint32_t*)(smp + HIo + byte)     = pk2(hx, hy);
        *(uint32_t*)(smp + HIo + byte + 4) = pk2(hz, hw);
        *(uint32_t*)(smp + LOo + byte)     = pk2(__float2bfloat16(v.x - __bfloat162float(hx)),
                                                 __float2bfloat16(v.y - __bfloat162float(hy)));
        *(uint32_t*)(smp + LOo + byte + 4) = pk2(__float2bfloat16(v.z - __bfloat162float(hz)),
                                                 __float2bfloat16(v.w - __bfloat162float(hw)));
    }
}

__global__ void __launch_bounds__(256, 1) __cluster_dims__(2, 1, 1)
dec_kernel(const float* __restrict__ z_in, const float* __restrict__ z_tar,
           const float* __restrict__ bihd, const float* __restrict__ bhhd,
           const int* __restrict__ tf_ptr, float* __restrict__ out) {
    extern __shared__ unsigned char smp[];
    const uint32_t SB = (uint32_t)__cvta_generic_to_shared(smp);
    const int tid = threadIdx.x, w = tid >> 5, lane = tid & 31, g = lane >> 2, tq = lane & 3;
    uint32_t rank; asm("mov.u32 %0, %%cluster_ctarank;" : "=r"(rank));
    const int half = (int)rank, pair = blockIdx.x >> 1;
    const int b0 = pair * 64, chb = half * 64;
    const bool tf = (*tf_ptr != 0);

    for (int i = tid; i < 9216; i += 256)
        cp_async16(smp + i * 16, g_Bres[half] + i * 16);
    cp_commit();

    load_act(z_in + ((size_t)b0 * ISEQ + ISEQ - 1) * F_, (size_t)ISEQ * F_, smp, SXHI, SXLO, tid);
    load_act(g_h0 + (size_t)b0 * F_, F_, smp, SHHI, SHLO, tid);

    float hprev[4][2][2];
#pragma unroll
    for (int mt = 0; mt < 4; mt++)
#pragma unroll
        for (int rh = 0; rh < 2; rh++)
#pragma unroll
            for (int e = 0; e < 2; e++)
                hprev[mt][rh][e] = g_h0[(size_t)(b0 + 16 * mt + g + 8 * rh) * 128
                                        + chb + 8 * w + 2 * tq + e];
    float br[2], bz[2], bni[2], bnh[2];
#pragma unroll
    for (int e = 0; e < 2; e++) {
        int ch = chb + 8 * w + 2 * tq + e;
        br[e] = bihd[ch] + bhhd[ch];
        bz[e] = bihd[128 + ch] + bhhd[128 + ch];
        bni[e] = bihd[256 + ch];
        bnh[e] = bhhd[256 + ch];
    }
    const uint32_t swz = (uint32_t)((g & 4) << 2);
    uint32_t bofs[3], blo_ofs[3];
#pragma unroll
    for (int nt = 0; nt < 3; nt++) {
        int col = nt * 64 + 8 * w + g;
        bofs[nt]    = (uint32_t)(col * 32) + (((uint32_t)tq * 4) ^ swz);
        blo_ofs[nt] = (uint32_t)(col * 32 + tq * 4);
    }
    const uint32_t a_ofs = (uint32_t)(g * 272 + tq * 4);
    const unsigned char* bloG = g_B0lo[half];
    const uint32_t pHHI = mapa_u32(SB + SHHI, rank ^ 1);
    const uint32_t pHLO = mapa_u32(SB + SHLO, rank ^ 1);
    cp_wait0();

#pragma unroll 1
    for (int t = 0; t < PSEQ; t++) {
        CSYNC();   // tiles (incl. peer DSMEM writes of step t-1) visible cluster-wide
        float C[4][4][4];
#pragma unroll
        for (int a = 0; a < 4; a++)
#pragma unroll
            for (int b = 0; b < 4; b++)
#pragma unroll
                for (int cc = 0; cc < 4; cc++) C[a][b][cc] = 0.0f;
        const bool use_x = (t == 0) || tf;
#pragma unroll
        for (int gm = 0; gm < 2; gm++) {
            const uint32_t ahB = SB + (uint32_t)((gm == 0 && use_x) ? SXHI : SHHI) + a_ofs;
            const uint32_t alB = SB + (uint32_t)((gm == 0 && use_x) ? SXLO : SHLO) + a_ofs;
            const uint32_t bhB = SB + (uint32_t)(gm * 49152);
            const uint32_t blB = SB + 98304u;
#pragma unroll 1
            for (int kt = 0; kt < 8; kt++) {
                const uint32_t ko = (uint32_t)kt * 6144;
                uint32_t bl[3][2], bh[3][2];
                if (gm == 0) {
#pragma unroll
                    for (int nt = 0; nt < 3; nt++) {
                        const uint32_t* p = (const uint32_t*)(bloG + ko + blo_ofs[nt]);
                        bl[nt][0] = __ldg(p); bl[nt][1] = __ldg(p + 4);
                    }
                } else {
#pragma unroll
                    for (int nt = 0; nt < 3; nt++) {
                        uint32_t a0 = blB + ko + bofs[nt];
                        bl[nt][0] = lds32(a0); bl[nt][1] = lds32(a0 ^ 16u);
                    }
                }
#pragma unroll
                for (int nt = 0; nt < 3; nt++) {
                    uint32_t a0 = bhB + ko + bofs[nt];
                    bh[nt][0] = lds32(a0); bh[nt][1] = lds32(a0 ^ 16u);
                }
                uint32_t ahi[4][4], alo[4][4];
#pragma unroll
                for (int mt = 0; mt < 4; mt++) {
                    uint32_t ba = ahB + (uint32_t)(mt * 4352 + kt * 32);
                    ahi[mt][0] = lds32(ba);        ahi[mt][1] = lds32(ba + 2176);
                    ahi[mt][2] = lds32(ba + 16);   ahi[mt][3] = lds32(ba + 2192);
                    uint32_t bb = alB + (uint32_t)(mt * 4352 + kt * 32);
                    alo[mt][0] = lds32(bb);        alo[mt][1] = lds32(bb + 2176);
                    alo[mt][2] = lds32(bb + 16);   alo[mt][3] = lds32(bb + 2192);
                }
#pragma unroll
                for (int nt = 0; nt < 3; nt++) {
                    const int ci = (gm == 0 || nt < 2) ? nt : 3;
#pragma unroll
                    for (int mt = 0; mt < 4; mt++) {
                        mma16816(C[ci][mt], ahi[mt], bh[nt]);
                        mma16816(C[ci][mt], alo[mt], bh[nt]);
                        mma16816(C[ci][mt], ahi[mt], bl[nt]);
                    }
                }
            }
        }
        CSYNC();   // cluster-wide: all tile reads done before tiles are rewritten

#pragma unroll
        for (int mt = 0; mt < 4; mt++)
#pragma unroll
            for (int rh = 0; rh < 2; rh++) {
                const int row = 16 * mt + g + 8 * rh;
                const int ch0 = chb + 8 * w + 2 * tq;
                float hv[2]; __nv_bfloat16 hh[2], hl[2];
#pragma unroll
                for (int e = 0; e < 2; e++) {
                    int fi = rh * 2 + e;
                    float rr = sigf(C[0][mt][fi] + br[e]);
                    float zz = sigf(C[1][mt][fi] + bz[e]);
                    float nn = tanhf(C[2][mt][fi] + bni[e] + rr * (C[3][mt][fi] + bnh[e]));
                    float h = (1.0f - zz) * nn + zz * hprev[mt][rh][e];
                    hprev[mt][rh][e] = h;
                    hv[e] = h;
                    hh[e] = __float2bfloat16(h);
                    hl[e] = __float2bfloat16(h - __bfloat162float(hh[e]));
                }
                const uint32_t byte = (uint32_t)(row * 272 + ch0 * 2);
                *(uint32_t*)(smp + SHHI + byte) = pk2(hh[0], hh[1]);
                *(uint32_t*)(smp + SHLO + byte) = pk2(hl[0], hl[1]);
                stc32(pHHI + byte, pk2(hh[0], hh[1]));
                stc32(pHLO + byte, pk2(hl[0], hl[1]));
                *(float2*)(out + ((size_t)(b0 + row) * PSEQ + t) * F_ + ch0)
                    = make_float2(hv[0], hv[1]);
            }
        if (tf && (t + 1 < PSEQ))
            load_act(z_tar + ((size_t)b0 * PSEQ + t) * F_, (size_t)PSEQ * F_, smp, SXHI, SXLO, tid);
    }
    CSYNC();   // no CTA exits while peer DSMEM stores may be in flight
}

// ---------------- launch ----------------
extern "C" void kernel_launch(void* const* d_in, const int* in_sizes, int n_in,
                              void* d_out, int out_size) {
    const float* z_in  = (const float*)d_in[0];
    const float* z_tar = (const float*)d_in[1];
    const float* Wihe  = (const float*)d_in[2];
    const float* bihe  = (const float*)d_in[4];
    const float* bhhe  = (const float*)d_in[5];
    const float* Wfc   = (const float*)d_in[6];
    const float* bfc   = (const float*)d_in[7];
    const float* Wihd  = (const float*)d_in[8];
    const float* Whhd  = (const float*)d_in[9];
    const float* bihd  = (const float*)d_in[10];
    const float* bhhd  = (const float*)d_in[11];
    const int*   tf    = (const int*)d_in[12];
    float* out = (float*)d_out;

    prep_kernel<<<896, 256>>>(Wihe, Wfc, Wihd, Whhd);

    const int ENC_SMEM = (12288 + 128 * XST + 256 * XST) * 4;
    cudaFuncSetAttribute(enc_kernel, cudaFuncAttributeMaxDynamicSharedMemorySize, ENC_SMEM);
    enc_kernel<<<128, 256, ENC_SMEM>>>(z_in, bihe, bhhe, bfc);

    cudaFuncSetAttribute(dec_kernel, cudaFuncAttributeMaxDynamicSharedMemorySize, SMDEC);
    dec_kernel<<<128, 256, SMDEC>>>(z_in, z_tar, bihd, bhhd, tf, out);
}

// round 9
// speedup vs baseline: 2.6730x; 1.0628x over previous
#include <cuda_runtime.h>
#include <cuda_bf16.h>
#include <cuda_fp16.h>
#include <cstdint>
#include <cstddef>

#define BATCH 4096
#define F_ 128
#define H_ 256
#define ISEQ 96
#define PSEQ 48
#define XST 36
// dec SMEM byte offsets: B blobs | X hi/lo | H stage0 hi/lo | H stage1 hi/lo
#define SXHI 98304
#define SXLO 115712
#define SMDEC 202752

__device__ float g_WencT[128 * 768];
__device__ float g_WfcT [256 * 128];
__device__ float g_h0   [BATCH * F_];
__device__ __align__(128) unsigned char g_Bres[2][98304]; // Wih_h | Whh_h (fp16) per half

__device__ __forceinline__ float sigf(float x) { return 1.0f / (1.0f + __expf(-x)); }
__device__ __forceinline__ void cp_async16(void* sdst, const void* gsrc) {
    unsigned sa = (unsigned)__cvta_generic_to_shared(sdst);
    asm volatile("cp.async.cg.shared.global [%0], [%1], 16;" :: "r"(sa), "l"(gsrc));
}
__device__ __forceinline__ void cp_commit() { asm volatile("cp.async.commit_group;"); }
__device__ __forceinline__ void cp_wait1()  { asm volatile("cp.async.wait_group 1;"); }
__device__ __forceinline__ void cp_wait0()  { asm volatile("cp.async.wait_group 0;"); }
__device__ __forceinline__ uint32_t lds32(uint32_t a) {
    uint32_t v; asm volatile("ld.shared.b32 %0, [%1];" : "=r"(v) : "r"(a)); return v;
}
__device__ __forceinline__ void mma16816(float* c, const uint32_t* a, const uint32_t* b) {
    asm volatile("mma.sync.aligned.m16n8k16.row.col.f32.f16.f16.f32 "
                 "{%0,%1,%2,%3},{%4,%5,%6,%7},{%8,%9},{%0,%1,%2,%3};"
                 : "+f"(c[0]), "+f"(c[1]), "+f"(c[2]), "+f"(c[3])
                 : "r"(a[0]), "r"(a[1]), "r"(a[2]), "r"(a[3]), "r"(b[0]), "r"(b[1]));
}
__device__ __forceinline__ uint32_t mapa_u32(uint32_t a, uint32_t r) {
    uint32_t o; asm volatile("mapa.shared::cluster.u32 %0, %1, %2;" : "=r"(o) : "r"(a), "r"(r));
    return o;
}
__device__ __forceinline__ void stc32(uint32_t a, uint32_t v) {
    asm volatile("st.shared::cluster.u32 [%0], %1;" :: "r"(a), "r"(v) : "memory");
}
#define CSYNC() do { asm volatile("barrier.cluster.arrive.aligned;" ::: "memory"); \
                     asm volatile("barrier.cluster.wait.aligned;" ::: "memory"); } while (0)
__device__ __forceinline__ uint32_t pk2h(__half a, __half b) {
    return (uint32_t)__half_as_ushort(a) | ((uint32_t)__half_as_ushort(b) << 16);
}

// ---------------- prep ----------------
__global__ void prep_kernel(const float* __restrict__ Wihe, const float* __restrict__ Wfc,
                            const float* __restrict__ Wihd, const float* __restrict__ Whhd) {
    int idx = blockIdx.x * 256 + threadIdx.x;
    if (idx < 98304) {
        int k = idx / 768, s = idx - k * 768, c = s / 3, g = s - 3 * c;
        g_WencT[idx] = Wihe[(g * 256 + c) * 128 + k];
    } else if (idx < 131072) {
        int j = idx - 98304, k = j / 128, c = j - k * 128;
        g_WfcT[j] = Wfc[c * 256 + k];
    } else if (idx < 229376) {
        int j = idx - 131072;
        int half = j / 49152, r2 = j % 49152, gm = r2 / 24576, e = r2 % 24576;
        int col = e >> 7, k = e & 127;
        int gate = col >> 6, ch = half * 64 + (col & 63);
        const float* W = gm ? Whhd : Wihd;
        float w = W[(size_t)(gate * 128 + ch) * 128 + k];
        int kt = k >> 4, kk = k & 15;
        uint32_t sb = (uint32_t)(kt * 6144 + col * 32) + (uint32_t)((kk * 2) ^ ((col & 4) << 2));
        *(__half*)(g_Bres[half] + gm * 49152 + sb) = __float2half(w);
    }
}

// ---------------- encoder (fp32, proven) ----------------
__device__ __forceinline__ void load_chunk384(float* dst, const float* src, int stride, int tid) {
    int row = tid >> 4, col = (tid & 15) * 24;
    const float* s = src + (size_t)row * stride + col;
    float* d = dst + row * 384 + col;
#pragma unroll
    for (int i = 0; i < 6; i++) cp_async16(d + i * 4, s + i * 4);
}
__device__ __forceinline__ void load_chunk128(float* dst, const float* src, int tid) {
    int row = tid >> 4, col = (tid & 15) * 8;
    cp_async16(dst + row * 128 + col, src + row * 128 + col);
    cp_async16(dst + row * 128 + col + 4, src + row * 128 + col + 4);
}
__device__ __forceinline__ void gemm_x_full(const float* A, const float* Bt,
                                            int tx, int ty, float (&acc)[4][12]) {
#pragma unroll
    for (int k = 0; k < 16; k++) {
        float4 av = *(const float4*)(A + k * XST + 4 * ty);
        const float* bp = Bt + k * 384 + 12 * tx;
        float4 b0 = *(const float4*)bp, b1 = *(const float4*)(bp + 4), b2 = *(const float4*)(bp + 8);
        float aa[4] = {av.x, av.y, av.z, av.w};
        float bb[12] = {b0.x,b0.y,b0.z,b0.w,b1.x,b1.y,b1.z,b1.w,b2.x,b2.y,b2.z,b2.w};
#pragma unroll
        for (int r = 0; r < 4; r++)
#pragma unroll
            for (int j = 0; j < 12; j++) acc[r][j] = fmaf(aa[r], bb[j], acc[r][j]);
    }
}
__device__ __forceinline__ void gemm_fc(const float* A, const float* Bt,
                                        int tx, int ty, float (&acc)[4][4]) {
#pragma unroll
    for (int k = 0; k < 16; k++) {
        float4 av = *(const float4*)(A + k * XST + 4 * ty);
        float4 bv = *(const float4*)(Bt + k * 128 + 4 * tx);
        float aa[4] = {av.x, av.y, av.z, av.w};
        float bb[4] = {bv.x, bv.y, bv.z, bv.w};
#pragma unroll
        for (int r = 0; r < 4; r++)
#pragma unroll
            for (int j = 0; j < 4; j++) acc[r][j] = fmaf(aa[r], bb[j], acc[r][j]);
    }
}

__global__ void __launch_bounds__(256, 1)
enc_kernel(const float* __restrict__ z_in, const float* __restrict__ bihe,
           const float* __restrict__ bhhe, const float* __restrict__ bfc) {
    extern __shared__ float sm[];
    float* Bs = sm;
    float* xs = sm + 12288;
    float* he = xs + 128 * XST;
    const int tid = threadIdx.x, tx = tid & 31, ty = tid >> 5;
    const int b0 = blockIdx.x * 32;
    {
        int m = tid & 31, f0 = (tid >> 5) * 16;
        const float4* s = (const float4*)(z_in + ((size_t)(b0 + m) * ISEQ + ISEQ - 1) * F_ + f0);
        float4 v0 = s[0], v1 = s[1], v2 = s[2], v3 = s[3];
        float vv[16] = {v0.x,v0.y,v0.z,v0.w,v1.x,v1.y,v1.z,v1.w,v2.x,v2.y,v2.z,v2.w,v3.x,v3.y,v3.z,v3.w};
#pragma unroll
        for (int i = 0; i < 16; i++) xs[(f0 + i) * XST + m] = vv[i];
    }
    __syncthreads();
#pragma unroll 1
    for (int cc = 0; cc < 2; cc++) {
        float acc[4][12];
#pragma unroll
        for (int r = 0; r < 4; r++)
#pragma unroll
            for (int j = 0; j < 12; j++) acc[r][j] = 0.0f;
        load_chunk384(Bs, g_WencT + cc * 384, 768, tid);
        cp_commit();
#pragma unroll 1
        for (int ch = 0; ch < 8; ch++) {
            if (ch < 7) {
                load_chunk384(Bs + ((ch + 1) & 1) * 6144,
                              g_WencT + (size_t)(ch + 1) * 16 * 768 + cc * 384, 768, tid);
                cp_commit(); cp_wait1();
            } else cp_wait0();
            __syncthreads();
            gemm_x_full(xs + ch * 16 * XST, Bs + (ch & 1) * 6144, tx, ty, acc);
            __syncthreads();
        }
#pragma unroll
        for (int cj = 0; cj < 4; cj++) {
            int c = cc * 128 + 4 * tx + cj;
            float br = bihe[c] + bhhe[c];
            float bz = bihe[H_ + c] + bhhe[H_ + c];
            float bni = bihe[2 * H_ + c], bnh = bhhe[2 * H_ + c];
#pragma unroll
            for (int r = 0; r < 4; r++) {
                float rr = sigf(acc[r][3 * cj] + br);
                float zz = sigf(acc[r][3 * cj + 1] + bz);
                float nn = tanhf(acc[r][3 * cj + 2] + bni + rr * bnh);
                he[c * XST + 4 * ty + r] = (1.0f - zz) * nn;
            }
        }
    }
    {
        float a2[4][4];
#pragma unroll
        for (int r = 0; r < 4; r++)
#pragma unroll
            for (int j = 0; j < 4; j++) a2[r][j] = 0.0f;
        load_chunk128(Bs, g_WfcT, tid);
        cp_commit();
#pragma unroll 1
        for (int ch = 0; ch < 16; ch++) {
            if (ch < 15) {
                load_chunk128(Bs + ((ch + 1) & 1) * 6144, g_WfcT + (ch + 1) * 16 * 128, tid);
                cp_commit(); cp_wait1();
            } else cp_wait0();
            __syncthreads();
            gemm_fc(he + ch * 16 * XST, Bs + (ch & 1) * 6144, tx, ty, a2);
            __syncthreads();
        }
#pragma unroll
        for (int r = 0; r < 4; r++) {
            float4 o = make_float4(fmaxf(a2[r][0] + bfc[4 * tx + 0], 0.0f),
                                   fmaxf(a2[r][1] + bfc[4 * tx + 1], 0.0f),
                                   fmaxf(a2[r][2] + bfc[4 * tx + 2], 0.0f),
                                   fmaxf(a2[r][3] + bfc[4 * tx + 3], 0.0f));
            *(float4*)(g_h0 + (size_t)(b0 + 4 * ty + r) * 128 + 4 * tx) = o;
        }
    }
}

// ---------------- decoder: pair-split fp16 mma.sync, A hi/lo split, B single ----------------
// act tile: 64 rows x 128 ch fp16, row stride 136 elems (272B).
__device__ __forceinline__ void load_act(const float* src, size_t rowStride,
                                         unsigned char* smp, int HIo, int LOo, int tid) {
    int m = tid >> 2, f0 = (tid & 3) * 32;
    const float4* s = (const float4*)(src + (size_t)m * rowStride + f0);
#pragma unroll
    for (int i = 0; i < 8; i++) {
        float4 v = s[i];
        __half hx = __float2half(v.x), hy = __float2half(v.y);
        __half hz = __float2half(v.z), hw = __float2half(v.w);
        int byte = m * 272 + (f0 + 4 * i) * 2;
        *(uint32_t*)(smp + HIo + byte)     = pk2h(hx, hy);
        *(uint32_t*)(smp + HIo + byte + 4) = pk2h(hz, hw);
        *(uint32_t*)(smp + LOo + byte)     = pk2h(__float2half(v.x - __half2float(hx)),
                                                  __float2half(v.y - __half2float(hy)));
        *(uint32_t*)(smp + LOo + byte + 4) = pk2h(__float2half(v.z - __half2float(hz)),
                                                  __float2half(v.w - __half2float(hw)));
    }
}

__global__ void __launch_bounds__(256, 1) __cluster_dims__(2, 1, 1)
dec_kernel(const float* __restrict__ z_in, const float* __restrict__ z_tar,
           const float* __restrict__ bihd, const float* __restrict__ bhhd,
           const int* __restrict__ tf_ptr, float* __restrict__ out) {
    extern __shared__ unsigned char smp[];
    const uint32_t SB = (uint32_t)__cvta_generic_to_shared(smp);
    const int tid = threadIdx.x, w = tid >> 5, lane = tid & 31, g = lane >> 2, tq = lane & 3;
    uint32_t rank; asm("mov.u32 %0, %%cluster_ctarank;" : "=r"(rank));
    const int half = (int)rank, pair = blockIdx.x >> 1;
    const int b0 = pair * 64, chb = half * 64;
    const bool tf = (*tf_ptr != 0);
    const int SH_HI[2] = {133120, 167936};
    const int SH_LO[2] = {150528, 185344};

    for (int i = tid; i < 6144; i += 256)
        cp_async16(smp + i * 16, g_Bres[half] + i * 16);
    cp_commit();

    load_act(z_in + ((size_t)b0 * ISEQ + ISEQ - 1) * F_, (size_t)ISEQ * F_, smp, SXHI, SXLO, tid);
    load_act(g_h0 + (size_t)b0 * F_, F_, smp, SH_HI[0], SH_LO[0], tid);

    float hprev[4][2][2];
#pragma unroll
    for (int mt = 0; mt < 4; mt++)
#pragma unroll
        for (int rh = 0; rh < 2; rh++)
#pragma unroll
            for (int e = 0; e < 2; e++)
                hprev[mt][rh][e] = g_h0[(size_t)(b0 + 16 * mt + g + 8 * rh) * 128
                                        + chb + 8 * w + 2 * tq + e];
    float br[2], bz[2], bni[2], bnh[2];
#pragma unroll
    for (int e = 0; e < 2; e++) {
        int ch = chb + 8 * w + 2 * tq + e;
        br[e] = bihd[ch] + bhhd[ch];
        bz[e] = bihd[128 + ch] + bhhd[128 + ch];
        bni[e] = bihd[256 + ch];
        bnh[e] = bhhd[256 + ch];
    }
    const uint32_t swz = (uint32_t)((g & 4) << 2);
    uint32_t bofs[3];
#pragma unroll
    for (int nt = 0; nt < 3; nt++) {
        int col = nt * 64 + 8 * w + g;
        bofs[nt] = (uint32_t)(col * 32) + (((uint32_t)tq * 4) ^ swz);
    }
    const uint32_t a_ofs = (uint32_t)(g * 272 + tq * 4);
    uint32_t pHHI[2], pHLO[2];
#pragma unroll
    for (int st = 0; st < 2; st++) {
        pHHI[st] = mapa_u32(SB + (uint32_t)SH_HI[st], rank ^ 1);
        pHLO[st] = mapa_u32(SB + (uint32_t)SH_LO[st], rank ^ 1);
    }
    cp_wait0();

#pragma unroll 1
    for (int t = 0; t < PSEQ; t++) {
        CSYNC();   // step t-1 writes (own + peer DSMEM) visible; t-1 reads complete
        const int cur = t & 1, nxt = cur ^ 1;
        float C[4][4][4];
#pragma unroll
        for (int a = 0; a < 4; a++)
#pragma unroll
            for (int b = 0; b < 4; b++)
#pragma unroll
                for (int cc = 0; cc < 4; cc++) C[a][b][cc] = 0.0f;
        const bool use_x = (t == 0) || tf;
#pragma unroll
        for (int gm = 0; gm < 2; gm++) {
            const uint32_t ahB = SB + (uint32_t)((gm == 0 && use_x) ? SXHI : SH_HI[cur]) + a_ofs;
            const uint32_t alB = SB + (uint32_t)((gm == 0 && use_x) ? SXLO : SH_LO[cur]) + a_ofs;
            const uint32_t bhB = SB + (uint32_t)(gm * 49152);
#pragma unroll 1
            for (int kt = 0; kt < 8; kt++) {
                const uint32_t ko = (uint32_t)kt * 6144;
                uint32_t bh[3][2];
#pragma unroll
                for (int nt = 0; nt < 3; nt++) {
                    uint32_t a0 = bhB + ko + bofs[nt];
                    bh[nt][0] = lds32(a0); bh[nt][1] = lds32(a0 ^ 16u);
                }
                uint32_t ahi[4][4], alo[4][4];
#pragma unroll
                for (int mt = 0; mt < 4; mt++) {
                    uint32_t ba = ahB + (uint32_t)(mt * 4352 + kt * 32);
                    ahi[mt][0] = lds32(ba);        ahi[mt][1] = lds32(ba + 2176);
                    ahi[mt][2] = lds32(ba + 16);   ahi[mt][3] = lds32(ba + 2192);
                    uint32_t bb = alB + (uint32_t)(mt * 4352 + kt * 32);
                    alo[mt][0] = lds32(bb);        alo[mt][1] = lds32(bb + 2176);
                    alo[mt][2] = lds32(bb + 16);   alo[mt][3] = lds32(bb + 2192);
                }
#pragma unroll
                for (int nt = 0; nt < 3; nt++) {
                    const int ci = (gm == 0 || nt < 2) ? nt : 3;
#pragma unroll
                    for (int mt = 0; mt < 4; mt++) {
                        mma16816(C[ci][mt], ahi[mt], bh[nt]);
                        mma16816(C[ci][mt], alo[mt], bh[nt]);
                    }
                }
            }
        }

        // combine -> h stage nxt (own smem + peer DSMEM) + output
#pragma unroll
        for (int mt = 0; mt < 4; mt++)
#pragma unroll
            for (int rh = 0; rh < 2; rh++) {
                const int row = 16 * mt + g + 8 * rh;
                const int ch0 = chb + 8 * w + 2 * tq;
                float hv[2]; __half hh[2], hl[2];
#pragma unroll
                for (int e = 0; e < 2; e++) {
                    int fi = rh * 2 + e;
                    float rr = sigf(C[0][mt][fi] + br[e]);
                    float zz = sigf(C[1][mt][fi] + bz[e]);
                    float nn = tanhf(C[2][mt][fi] + bni[e] + rr * (C[3][mt][fi] + bnh[e]));
                    float h = (1.0f - zz) * nn + zz * hprev[mt][rh][e];
                    hprev[mt][rh][e] = h;
                    hv[e] = h;
                    hh[e] = __float2half(h);
                    hl[e] = __float2half(h - __half2float(hh[e]));
                }
                const uint32_t byte = (uint32_t)(row * 272 + ch0 * 2);
                *(uint32_t*)(smp + SH_HI[nxt] + byte) = pk2h(hh[0], hh[1]);
                *(uint32_t*)(smp + SH_LO[nxt] + byte) = pk2h(hl[0], hl[1]);
                stc32(pHHI[nxt] + byte, pk2h(hh[0], hh[1]));
                stc32(pHLO[nxt] + byte, pk2h(hl[0], hl[1]));
                *(float2*)(out + ((size_t)(b0 + row) * PSEQ + t) * F_ + ch0)
                    = make_float2(hv[0], hv[1]);
            }
        __syncthreads();   // all warps done reading X tile before rewrite
        if (tf && (t + 1 < PSEQ))
            load_act(z_tar + ((size_t)b0 * PSEQ + t) * F_, (size_t)PSEQ * F_, smp, SXHI, SXLO, tid);
    }
    CSYNC();   // no CTA exits while peer DSMEM stores may be in flight
}

// ---------------- launch ----------------
extern "C" void kernel_launch(void* const* d_in, const int* in_sizes, int n_in,
                              void* d_out, int out_size) {
    const float* z_in  = (const float*)d_in[0];
    const float* z_tar = (const float*)d_in[1];
    const float* Wihe  = (const float*)d_in[2];
    const float* bihe  = (const float*)d_in[4];
    const float* bhhe  = (const float*)d_in[5];
    const float* Wfc   = (const float*)d_in[6];
    const float* bfc   = (const float*)d_in[7];
    const float* Wihd  = (const float*)d_in[8];
    const float* Whhd  = (const float*)d_in[9];
    const float* bihd  = (const float*)d_in[10];
    const float* bhhd  = (const float*)d_in[11];
    const int*   tf    = (const int*)d_in[12];
    float* out = (float*)d_out;

    prep_kernel<<<896, 256>>>(Wihe, Wfc, Wihd, Whhd);

    const int ENC_SMEM = (12288 + 128 * XST + 256 * XST) * 4;
    cudaFuncSetAttribute(enc_kernel, cudaFuncAttributeMaxDynamicSharedMemorySize, ENC_SMEM);
    enc_kernel<<<128, 256, ENC_SMEM>>>(z_in, bihe, bhhe, bfc);

    cudaFuncSetAttribute(dec_kernel, cudaFuncAttributeMaxDynamicSharedMemorySize, SMDEC);
    dec_kernel<<<128, 256, SMDEC>>>(z_in, z_tar, bihd, bhhd, tf, out);
}

// round 10
// speedup vs baseline: 3.7420x; 1.3999x over previous
#include <cuda_runtime.h>
#include <cuda_bf16.h>
#include <cuda_fp16.h>
#include <cstdint>
#include <cstddef>

#define BATCH 4096
#define F_ 128
#define H_ 256
#define ISEQ 96
#define PSEQ 48
#define XST 36
// dec SMEM byte offsets: B blobs (98304) | X | H stage0 | H stage1 (17408 each)
#define SX   98304
#define SMDEC 150528

__device__ float g_WencT[128 * 768];
__device__ float g_WfcT [256 * 128];
__device__ float g_h0   [BATCH * F_];
__device__ __align__(128) unsigned char g_Bres[2][98304]; // Wih_h | Whh_h (fp16) per half

__device__ __forceinline__ float sigf(float x) { return 1.0f / (1.0f + __expf(-x)); }
__device__ __forceinline__ void cp_async16(void* sdst, const void* gsrc) {
    unsigned sa = (unsigned)__cvta_generic_to_shared(sdst);
    asm volatile("cp.async.cg.shared.global [%0], [%1], 16;" :: "r"(sa), "l"(gsrc));
}
__device__ __forceinline__ void cp_commit() { asm volatile("cp.async.commit_group;"); }
__device__ __forceinline__ void cp_wait1()  { asm volatile("cp.async.wait_group 1;"); }
__device__ __forceinline__ void cp_wait0()  { asm volatile("cp.async.wait_group 0;"); }
__device__ __forceinline__ uint32_t lds32(uint32_t a) {
    uint32_t v; asm volatile("ld.shared.b32 %0, [%1];" : "=r"(v) : "r"(a)); return v;
}
__device__ __forceinline__ void mma16816(float* c, const uint32_t* a, const uint32_t* b) {
    asm volatile("mma.sync.aligned.m16n8k16.row.col.f32.f16.f16.f32 "
                 "{%0,%1,%2,%3},{%4,%5,%6,%7},{%8,%9},{%0,%1,%2,%3};"
                 : "+f"(c[0]), "+f"(c[1]), "+f"(c[2]), "+f"(c[3])
                 : "r"(a[0]), "r"(a[1]), "r"(a[2]), "r"(a[3]), "r"(b[0]), "r"(b[1]));
}
__device__ __forceinline__ uint32_t mapa_u32(uint32_t a, uint32_t r) {
    uint32_t o; asm volatile("mapa.shared::cluster.u32 %0, %1, %2;" : "=r"(o) : "r"(a), "r"(r));
    return o;
}
__device__ __forceinline__ void stc32(uint32_t a, uint32_t v) {
    asm volatile("st.shared::cluster.u32 [%0], %1;" :: "r"(a), "r"(v) : "memory");
}
#define CSYNC() do { asm volatile("barrier.cluster.arrive.aligned;" ::: "memory"); \
                     asm volatile("barrier.cluster.wait.aligned;" ::: "memory"); } while (0)
__device__ __forceinline__ uint32_t pk2h(__half a, __half b) {
    return (uint32_t)__half_as_ushort(a) | ((uint32_t)__half_as_ushort(b) << 16);
}

// ---------------- prep ----------------
__global__ void prep_kernel(const float* __restrict__ Wihe, const float* __restrict__ Wfc,
                            const float* __restrict__ Wihd, const float* __restrict__ Whhd) {
    int idx = blockIdx.x * 256 + threadIdx.x;
    if (idx < 98304) {
        int k = idx / 768, s = idx - k * 768, c = s / 3, g = s - 3 * c;
        g_WencT[idx] = Wihe[(g * 256 + c) * 128 + k];
    } else if (idx < 131072) {
        int j = idx - 98304, k = j / 128, c = j - k * 128;
        g_WfcT[j] = Wfc[c * 256 + k];
    } else if (idx < 229376) {
        int j = idx - 131072;
        int half = j / 49152, r2 = j % 49152, gm = r2 / 24576, e = r2 % 24576;
        int col = e >> 7, k = e & 127;
        int gate = col >> 6, ch = half * 64 + (col & 63);
        const float* W = gm ? Whhd : Wihd;
        float w = W[(size_t)(gate * 128 + ch) * 128 + k];
        int kt = k >> 4, kk = k & 15;
        uint32_t sb = (uint32_t)(kt * 6144 + col * 32) + (uint32_t)((kk * 2) ^ ((col & 4) << 2));
        *(__half*)(g_Bres[half] + gm * 49152 + sb) = __float2half(w);
    }
}

// ---------------- encoder (fp32, proven) ----------------
__device__ __forceinline__ void load_chunk384(float* dst, const float* src, int stride, int tid) {
    int row = tid >> 4, col = (tid & 15) * 24;
    const float* s = src + (size_t)row * stride + col;
    float* d = dst + row * 384 + col;
#pragma unroll
    for (int i = 0; i < 6; i++) cp_async16(d + i * 4, s + i * 4);
}
__device__ __forceinline__ void load_chunk128(float* dst, const float* src, int tid) {
    int row = tid >> 4, col = (tid & 15) * 8;
    cp_async16(dst + row * 128 + col, src + row * 128 + col);
    cp_async16(dst + row * 128 + col + 4, src + row * 128 + col + 4);
}
__device__ __forceinline__ void gemm_x_full(const float* A, const float* Bt,
                                            int tx, int ty, float (&acc)[4][12]) {
#pragma unroll
    for (int k = 0; k < 16; k++) {
        float4 av = *(const float4*)(A + k * XST + 4 * ty);
        const float* bp = Bt + k * 384 + 12 * tx;
        float4 b0 = *(const float4*)bp, b1 = *(const float4*)(bp + 4), b2 = *(const float4*)(bp + 8);
        float aa[4] = {av.x, av.y, av.z, av.w};
        float bb[12] = {b0.x,b0.y,b0.z,b0.w,b1.x,b1.y,b1.z,b1.w,b2.x,b2.y,b2.z,b2.w};
#pragma unroll
        for (int r = 0; r < 4; r++)
#pragma unroll
            for (int j = 0; j < 12; j++) acc[r][j] = fmaf(aa[r], bb[j], acc[r][j]);
    }
}
__device__ __forceinline__ void gemm_fc(const float* A, const float* Bt,
                                        int tx, int ty, float (&acc)[4][4]) {
#pragma unroll
    for (int k = 0; k < 16; k++) {
        float4 av = *(const float4*)(A + k * XST + 4 * ty);
        float4 bv = *(const float4*)(Bt + k * 128 + 4 * tx);
        float aa[4] = {av.x, av.y, av.z, av.w};
        float bb[4] = {bv.x, bv.y, bv.z, bv.w};
#pragma unroll
        for (int r = 0; r < 4; r++)
#pragma unroll
            for (int j = 0; j < 4; j++) acc[r][j] = fmaf(aa[r], bb[j], acc[r][j]);
    }
}

__global__ void __launch_bounds__(256, 1)
enc_kernel(const float* __restrict__ z_in, const float* __restrict__ bihe,
           const float* __restrict__ bhhe, const float* __restrict__ bfc) {
    extern __shared__ float sm[];
    float* Bs = sm;
    float* xs = sm + 12288;
    float* he = xs + 128 * XST;
    const int tid = threadIdx.x, tx = tid & 31, ty = tid >> 5;
    const int b0 = blockIdx.x * 32;
    {
        int m = tid & 31, f0 = (tid >> 5) * 16;
        const float4* s = (const float4*)(z_in + ((size_t)(b0 + m) * ISEQ + ISEQ - 1) * F_ + f0);
        float4 v0 = s[0], v1 = s[1], v2 = s[2], v3 = s[3];
        float vv[16] = {v0.x,v0.y,v0.z,v0.w,v1.x,v1.y,v1.z,v1.w,v2.x,v2.y,v2.z,v2.w,v3.x,v3.y,v3.z,v3.w};
#pragma unroll
        for (int i = 0; i < 16; i++) xs[(f0 + i) * XST + m] = vv[i];
    }
    __syncthreads();
#pragma unroll 1
    for (int cc = 0; cc < 2; cc++) {
        float acc[4][12];
#pragma unroll
        for (int r = 0; r < 4; r++)
#pragma unroll
            for (int j = 0; j < 12; j++) acc[r][j] = 0.0f;
        load_chunk384(Bs, g_WencT + cc * 384, 768, tid);
        cp_commit();
#pragma unroll 1
        for (int ch = 0; ch < 8; ch++) {
            if (ch < 7) {
                load_chunk384(Bs + ((ch + 1) & 1) * 6144,
                              g_WencT + (size_t)(ch + 1) * 16 * 768 + cc * 384, 768, tid);
                cp_commit(); cp_wait1();
            } else cp_wait0();
            __syncthreads();
            gemm_x_full(xs + ch * 16 * XST, Bs + (ch & 1) * 6144, tx, ty, acc);
            __syncthreads();
        }
#pragma unroll
        for (int cj = 0; cj < 4; cj++) {
            int c = cc * 128 + 4 * tx + cj;
            float br = bihe[c] + bhhe[c];
            float bz = bihe[H_ + c] + bhhe[H_ + c];
            float bni = bihe[2 * H_ + c], bnh = bhhe[2 * H_ + c];
#pragma unroll
            for (int r = 0; r < 4; r++) {
                float rr = sigf(acc[r][3 * cj] + br);
                float zz = sigf(acc[r][3 * cj + 1] + bz);
                float nn = tanhf(acc[r][3 * cj + 2] + bni + rr * bnh);
                he[c * XST + 4 * ty + r] = (1.0f - zz) * nn;
            }
        }
    }
    {
        float a2[4][4];
#pragma unroll
        for (int r = 0; r < 4; r++)
#pragma unroll
            for (int j = 0; j < 4; j++) a2[r][j] = 0.0f;
        load_chunk128(Bs, g_WfcT, tid);
        cp_commit();
#pragma unroll 1
        for (int ch = 0; ch < 16; ch++) {
            if (ch < 15) {
                load_chunk128(Bs + ((ch + 1) & 1) * 6144, g_WfcT + (ch + 1) * 16 * 128, tid);
                cp_commit(); cp_wait1();
            } else cp_wait0();
            __syncthreads();
            gemm_fc(he + ch * 16 * XST, Bs + (ch & 1) * 6144, tx, ty, a2);
            __syncthreads();
        }
#pragma unroll
        for (int r = 0; r < 4; r++) {
            float4 o = make_float4(fmaxf(a2[r][0] + bfc[4 * tx + 0], 0.0f),
                                   fmaxf(a2[r][1] + bfc[4 * tx + 1], 0.0f),
                                   fmaxf(a2[r][2] + bfc[4 * tx + 2], 0.0f),
                                   fmaxf(a2[r][3] + bfc[4 * tx + 3], 0.0f));
            *(float4*)(g_h0 + (size_t)(b0 + 4 * ty + r) * 128 + 4 * tx) = o;
        }
    }
}

// ---------------- decoder: pair-split fp16 mma.sync, single product ----------------
// act tile: 64 rows x 128 ch fp16, row stride 136 elems (272B).
__device__ __forceinline__ void load_act(const float* src, size_t rowStride,
                                         unsigned char* smp, int HIo, int tid) {
    int m = tid >> 2, f0 = (tid & 3) * 32;
    const float4* s = (const float4*)(src + (size_t)m * rowStride + f0);
#pragma unroll
    for (int i = 0; i < 8; i++) {
        float4 v = s[i];
        int byte = m * 272 + (f0 + 4 * i) * 2;
        *(uint32_t*)(smp + HIo + byte)     = pk2h(__float2half(v.x), __float2half(v.y));
        *(uint32_t*)(smp + HIo + byte + 4) = pk2h(__float2half(v.z), __float2half(v.w));
    }
}

__global__ void __launch_bounds__(256, 1) __cluster_dims__(2, 1, 1)
dec_kernel(const float* __restrict__ z_in, const float* __restrict__ z_tar,
           const float* __restrict__ bihd, const float* __restrict__ bhhd,
           const int* __restrict__ tf_ptr, float* __restrict__ out) {
    extern __shared__ unsigned char smp[];
    const uint32_t SB = (uint32_t)__cvta_generic_to_shared(smp);
    const int tid = threadIdx.x, w = tid >> 5, lane = tid & 31, g = lane >> 2, tq = lane & 3;
    uint32_t rank; asm("mov.u32 %0, %%cluster_ctarank;" : "=r"(rank));
    const int half = (int)rank, pair = blockIdx.x >> 1;
    const int b0 = pair * 64, chb = half * 64;
    const bool tf = (*tf_ptr != 0);
    const int SH[2] = {115712, 133120};

    for (int i = tid; i < 6144; i += 256)
        cp_async16(smp + i * 16, g_Bres[half] + i * 16);
    cp_commit();

    load_act(z_in + ((size_t)b0 * ISEQ + ISEQ - 1) * F_, (size_t)ISEQ * F_, smp, SX, tid);
    load_act(g_h0 + (size_t)b0 * F_, F_, smp, SH[0], tid);

    float hprev[4][2][2];
#pragma unroll
    for (int mt = 0; mt < 4; mt++)
#pragma unroll
        for (int rh = 0; rh < 2; rh++)
#pragma unroll
            for (int e = 0; e < 2; e++)
                hprev[mt][rh][e] = g_h0[(size_t)(b0 + 16 * mt + g + 8 * rh) * 128
                                        + chb + 8 * w + 2 * tq + e];
    float br[2], bz[2], bni[2], bnh[2];
#pragma unroll
    for (int e = 0; e < 2; e++) {
        int ch = chb + 8 * w + 2 * tq + e;
        br[e] = bihd[ch] + bhhd[ch];
        bz[e] = bihd[128 + ch] + bhhd[128 + ch];
        bni[e] = bihd[256 + ch];
        bnh[e] = bhhd[256 + ch];
    }
    const uint32_t swz = (uint32_t)((g & 4) << 2);
    uint32_t bofs[3];
#pragma unroll
    for (int nt = 0; nt < 3; nt++) {
        int col = nt * 64 + 8 * w + g;
        bofs[nt] = (uint32_t)(col * 32) + (((uint32_t)tq * 4) ^ swz);
    }
    const uint32_t a_ofs = (uint32_t)(g * 272 + tq * 4);
    uint32_t pH[2];
#pragma unroll
    for (int st = 0; st < 2; st++) pH[st] = mapa_u32(SB + (uint32_t)SH[st], rank ^ 1);
    cp_wait0();

#pragma unroll 1
    for (int t = 0; t < PSEQ; t++) {
        CSYNC();   // step t-1 writes (own + peer DSMEM) visible; t-1 reads complete
        const int cur = t & 1, nxt = cur ^ 1;
        float C[4][4][4];
#pragma unroll
        for (int a = 0; a < 4; a++)
#pragma unroll
            for (int b = 0; b < 4; b++)
#pragma unroll
                for (int cc = 0; cc < 4; cc++) C[a][b][cc] = 0.0f;
        const bool use_x = (t == 0) || tf;
#pragma unroll
        for (int gm = 0; gm < 2; gm++) {
            const uint32_t ahB = SB + (uint32_t)((gm == 0 && use_x) ? SX : SH[cur]) + a_ofs;
            const uint32_t bhB = SB + (uint32_t)(gm * 49152);
#pragma unroll 1
            for (int kt = 0; kt < 8; kt++) {
                const uint32_t ko = (uint32_t)kt * 6144;
                uint32_t bh[3][2];
#pragma unroll
                for (int nt = 0; nt < 3; nt++) {
                    uint32_t a0 = bhB + ko + bofs[nt];
                    bh[nt][0] = lds32(a0); bh[nt][1] = lds32(a0 ^ 16u);
                }
                uint32_t ahi[4][4];
#pragma unroll
                for (int mt = 0; mt < 4; mt++) {
                    uint32_t ba = ahB + (uint32_t)(mt * 4352 + kt * 32);
                    ahi[mt][0] = lds32(ba);        ahi[mt][1] = lds32(ba + 2176);
                    ahi[mt][2] = lds32(ba + 16);   ahi[mt][3] = lds32(ba + 2192);
                }
#pragma unroll
                for (int nt = 0; nt < 3; nt++) {
                    const int ci = (gm == 0 || nt < 2) ? nt : 3;
#pragma unroll
                    for (int mt = 0; mt < 4; mt++)
                        mma16816(C[ci][mt], ahi[mt], bh[nt]);
                }
            }
        }

        // combine -> h stage nxt (own smem + peer DSMEM) + output
#pragma unroll
        for (int mt = 0; mt < 4; mt++)
#pragma unroll
            for (int rh = 0; rh < 2; rh++) {
                const int row = 16 * mt + g + 8 * rh;
                const int ch0 = chb + 8 * w + 2 * tq;
                float hv[2]; __half hh[2];
#pragma unroll
                for (int e = 0; e < 2; e++) {
                    int fi = rh * 2 + e;
                    float rr = sigf(C[0][mt][fi] + br[e]);
                    float zz = sigf(C[1][mt][fi] + bz[e]);
                    float nn = tanhf(C[2][mt][fi] + bni[e] + rr * (C[3][mt][fi] + bnh[e]));
                    float h = (1.0f - zz) * nn + zz * hprev[mt][rh][e];
                    hprev[mt][rh][e] = h;
                    hv[e] = h;
                    hh[e] = __float2half(h);
                }
                const uint32_t byte = (uint32_t)(row * 272 + ch0 * 2);
                uint32_t pk = pk2h(hh[0], hh[1]);
                *(uint32_t*)(smp + SH[nxt] + byte) = pk;
                stc32(pH[nxt] + byte, pk);
                *(float2*)(out + ((size_t)(b0 + row) * PSEQ + t) * F_ + ch0)
                    = make_float2(hv[0], hv[1]);
            }
        __syncthreads();   // all warps done reading X tile before rewrite
        if (tf && (t + 1 < PSEQ))
            load_act(z_tar + ((size_t)b0 * PSEQ + t) * F_, (size_t)PSEQ * F_, smp, SX, tid);
    }
    CSYNC();   // no CTA exits while peer DSMEM stores may be in flight
}

// ---------------- launch ----------------
extern "C" void kernel_launch(void* const* d_in, const int* in_sizes, int n_in,
                              void* d_out, int out_size) {
    const float* z_in  = (const float*)d_in[0];
    const float* z_tar = (const float*)d_in[1];
    const float* Wihe  = (const float*)d_in[2];
    const float* bihe  = (const float*)d_in[4];
    const float* bhhe  = (const float*)d_in[5];
    const float* Wfc   = (const float*)d_in[6];
    const float* bfc   = (const float*)d_in[7];
    const float* Wihd  = (const float*)d_in[8];
    const float* Whhd  = (const float*)d_in[9];
    const float* bihd  = (const float*)d_in[10];
    const float* bhhd  = (const float*)d_in[11];
    const int*   tf    = (const int*)d_in[12];
    float* out = (float*)d_out;

    prep_kernel<<<896, 256>>>(Wihe, Wfc, Wihd, Whhd);

    const int ENC_SMEM = (12288 + 128 * XST + 256 * XST) * 4;
    cudaFuncSetAttribute(enc_kernel, cudaFuncAttributeMaxDynamicSharedMemorySize, ENC_SMEM);
    enc_kernel<<<128, 256, ENC_SMEM>>>(z_in, bihe, bhhe, bfc);

    cudaFuncSetAttribute(dec_kernel, cudaFuncAttributeMaxDynamicSharedMemorySize, SMDEC);
    dec_kernel<<<128, 256, SMDEC>>>(z_in, z_tar, bihd, bhhd, tf, out);
}

// round 13
// speedup vs baseline: 3.9954x; 1.0677x over previous
#include <cuda_runtime.h>
#include <cuda_bf16.h>
#include <cuda_fp16.h>
#include <cstdint>
#include <cstddef>

#define BATCH 4096
#define F_ 128
#define H_ 256
#define ISEQ 96
#define PSEQ 48
#define XST 36
// dec SMEM byte offsets: B blobs (98304) | X | H stage0 | H stage1 (17408 each)
#define SX   98304
#define SMDEC 150528

__device__ float g_WencT[128 * 768];
__device__ float g_WfcT [256 * 128];
__device__ float g_h0   [BATCH * F_];
__device__ __align__(128) unsigned char g_Bres[2][98304]; // Wih_h | Whh_h (fp16) per half

__device__ __forceinline__ float sigf(float x) { return 1.0f / (1.0f + __expf(-x)); }
__device__ __forceinline__ void cp_async16(void* sdst, const void* gsrc) {
    unsigned sa = (unsigned)__cvta_generic_to_shared(sdst);
    asm volatile("cp.async.cg.shared.global [%0], [%1], 16;" :: "r"(sa), "l"(gsrc));
}
__device__ __forceinline__ void cp_commit() { asm volatile("cp.async.commit_group;"); }
__device__ __forceinline__ void cp_wait1()  { asm volatile("cp.async.wait_group 1;"); }
__device__ __forceinline__ void cp_wait0()  { asm volatile("cp.async.wait_group 0;"); }
__device__ __forceinline__ uint32_t lds32(uint32_t a) {
    uint32_t v; asm volatile("ld.shared.b32 %0, [%1];" : "=r"(v) : "r"(a)); return v;
}
__device__ __forceinline__ void ldmx4(uint32_t* r, uint32_t addr) {
    asm volatile("ldmatrix.sync.aligned.m8n8.x4.shared.b16 {%0,%1,%2,%3}, [%4];"
                 : "=r"(r[0]), "=r"(r[1]), "=r"(r[2]), "=r"(r[3]) : "r"(addr));
}
__device__ __forceinline__ void mma16816(float* c, const uint32_t* a, const uint32_t* b) {
    asm volatile("mma.sync.aligned.m16n8k16.row.col.f32.f16.f16.f32 "
                 "{%0,%1,%2,%3},{%4,%5,%6,%7},{%8,%9},{%0,%1,%2,%3};"
                 : "+f"(c[0]), "+f"(c[1]), "+f"(c[2]), "+f"(c[3])
                 : "r"(a[0]), "r"(a[1]), "r"(a[2]), "r"(a[3]), "r"(b[0]), "r"(b[1]));
}
__device__ __forceinline__ uint32_t mapa_u32(uint32_t a, uint32_t r) {
    uint32_t o; asm volatile("mapa.shared::cluster.u32 %0, %1, %2;" : "=r"(o) : "r"(a), "r"(r));
    return o;
}
__device__ __forceinline__ void stc32(uint32_t a, uint32_t v) {
    asm volatile("st.shared::cluster.u32 [%0], %1;" :: "r"(a), "r"(v) : "memory");
}
#define CSYNC() do { asm volatile("barrier.cluster.arrive.aligned;" ::: "memory"); \
                     asm volatile("barrier.cluster.wait.aligned;" ::: "memory"); } while (0)
__device__ __forceinline__ uint32_t pk2h(__half a, __half b) {
    return (uint32_t)__half_as_ushort(a) | ((uint32_t)__half_as_ushort(b) << 16);
}

// ---------------- prep ----------------
__global__ void prep_kernel(const float* __restrict__ Wihe, const float* __restrict__ Wfc,
                            const float* __restrict__ Wihd, const float* __restrict__ Whhd) {
    int idx = blockIdx.x * 256 + threadIdx.x;
    if (idx < 98304) {
        int k = idx / 768, s = idx - k * 768, c = s / 3, g = s - 3 * c;
        g_WencT[idx] = Wihe[(g * 256 + c) * 128 + k];
    } else if (idx < 131072) {
        int j = idx - 98304, k = j / 128, c = j - k * 128;
        g_WfcT[j] = Wfc[c * 256 + k];
    } else if (idx < 229376) {
        int j = idx - 131072;
        int half = j / 49152, r2 = j % 49152, gm = r2 / 24576, e = r2 % 24576;
        int col = e >> 7, k = e & 127;
        int gate = col >> 6, ch = half * 64 + (col & 63);
        const float* W = gm ? Whhd : Wihd;
        float w = W[(size_t)(gate * 128 + ch) * 128 + k];
        int kt = k >> 4, kk = k & 15;
        uint32_t sb = (uint32_t)(kt * 6144 + col * 32) + (uint32_t)((kk * 2) ^ ((col & 4) << 2));
        *(__half*)(g_Bres[half] + gm * 49152 + sb) = __float2half(w);
    }
}

// ---------------- encoder (fp32, proven) ----------------
__device__ __forceinline__ void load_chunk384(float* dst, const float* src, int stride, int tid) {
    int row = tid >> 4, col = (tid & 15) * 24;
    const float* s = src + (size_t)row * stride + col;
    float* d = dst + row * 384 + col;
#pragma unroll
    for (int i = 0; i < 6; i++) cp_async16(d + i * 4, s + i * 4);
}
__device__ __forceinline__ void load_chunk128(float* dst, const float* src, int tid) {
    int row = tid >> 4, col = (tid & 15) * 8;
    cp_async16(dst + row * 128 + col, src + row * 128 + col);
    cp_async16(dst + row * 128 + col + 4, src + row * 128 + col + 4);
}
__device__ __forceinline__ void gemm_x_full(const float* A, const float* Bt,
                                            int tx, int ty, float (&acc)[4][12]) {
#pragma unroll
    for (int k = 0; k < 16; k++) {
        float4 av = *(const float4*)(A + k * XST + 4 * ty);
        const float* bp = Bt + k * 384 + 12 * tx;
        float4 b0 = *(const float4*)bp, b1 = *(const float4*)(bp + 4), b2 = *(const float4*)(bp + 8);
        float aa[4] = {av.x, av.y, av.z, av.w};
        float bb[12] = {b0.x,b0.y,b0.z,b0.w,b1.x,b1.y,b1.z,b1.w,b2.x,b2.y,b2.z,b2.w};
#pragma unroll
        for (int r = 0; r < 4; r++)
#pragma unroll
            for (int j = 0; j < 12; j++) acc[r][j] = fmaf(aa[r], bb[j], acc[r][j]);
    }
}
__device__ __forceinline__ void gemm_fc(const float* A, const float* Bt,
                                        int tx, int ty, float (&acc)[4][4]) {
#pragma unroll
    for (int k = 0; k < 16; k++) {
        float4 av = *(const float4*)(A + k * XST + 4 * ty);
        float4 bv = *(const float4*)(Bt + k * 128 + 4 * tx);
        float aa[4] = {av.x, av.y, av.z, av.w};
        float bb[4] = {bv.x, bv.y, bv.z, bv.w};
#pragma unroll
        for (int r = 0; r < 4; r++)
#pragma unroll
            for (int j = 0; j < 4; j++) acc[r][j] = fmaf(aa[r], bb[j], acc[r][j]);
    }
}

__global__ void __launch_bounds__(256, 1)
enc_kernel(const float* __restrict__ z_in, const float* __restrict__ bihe,
           const float* __restrict__ bhhe, const float* __restrict__ bfc) {
    extern __shared__ float sm[];
    float* Bs = sm;
    float* xs = sm + 12288;
    float* he = xs + 128 * XST;
    const int tid = threadIdx.x, tx = tid & 31, ty = tid >> 5;
    const int b0 = blockIdx.x * 32;
    {
        int m = tid & 31, f0 = (tid >> 5) * 16;
        const float4* s = (const float4*)(z_in + ((size_t)(b0 + m) * ISEQ + ISEQ - 1) * F_ + f0);
        float4 v0 = s[0], v1 = s[1], v2 = s[2], v3 = s[3];
        float vv[16] = {v0.x,v0.y,v0.z,v0.w,v1.x,v1.y,v1.z,v1.w,v2.x,v2.y,v2.z,v2.w,v3.x,v3.y,v3.z,v3.w};
#pragma unroll
        for (int i = 0; i < 16; i++) xs[(f0 + i) * XST + m] = vv[i];
    }
    __syncthreads();
#pragma unroll 1
    for (int cc = 0; cc < 2; cc++) {
        float acc[4][12];
#pragma unroll
        for (int r = 0; r < 4; r++)
#pragma unroll
            for (int j = 0; j < 12; j++) acc[r][j] = 0.0f;
        load_chunk384(Bs, g_WencT + cc * 384, 768, tid);
        cp_commit();
#pragma unroll 1
        for (int ch = 0; ch < 8; ch++) {
            if (ch < 7) {
                load_chunk384(Bs + ((ch + 1) & 1) * 6144,
                              g_WencT + (size_t)(ch + 1) * 16 * 768 + cc * 384, 768, tid);
                cp_commit(); cp_wait1();
            } else cp_wait0();
            __syncthreads();
            gemm_x_full(xs + ch * 16 * XST, Bs + (ch & 1) * 6144, tx, ty, acc);
            __syncthreads();
        }
#pragma unroll
        for (int cj = 0; cj < 4; cj++) {
            int c = cc * 128 + 4 * tx + cj;
            float br = bihe[c] + bhhe[c];
            float bz = bihe[H_ + c] + bhhe[H_ + c];
            float bni = bihe[2 * H_ + c], bnh = bhhe[2 * H_ + c];
#pragma unroll
            for (int r = 0; r < 4; r++) {
                float rr = sigf(acc[r][3 * cj] + br);
                float zz = sigf(acc[r][3 * cj + 1] + bz);
                float nn = tanhf(acc[r][3 * cj + 2] + bni + rr * bnh);
                he[c * XST + 4 * ty + r] = (1.0f - zz) * nn;
            }
        }
    }
    {
        float a2[4][4];
#pragma unroll
        for (int r = 0; r < 4; r++)
#pragma unroll
            for (int j = 0; j < 4; j++) a2[r][j] = 0.0f;
        load_chunk128(Bs, g_WfcT, tid);
        cp_commit();
#pragma unroll 1
        for (int ch = 0; ch < 16; ch++) {
            if (ch < 15) {
                load_chunk128(Bs + ((ch + 1) & 1) * 6144, g_WfcT + (ch + 1) * 16 * 128, tid);
                cp_commit(); cp_wait1();
            } else cp_wait0();
            __syncthreads();
            gemm_fc(he + ch * 16 * XST, Bs + (ch & 1) * 6144, tx, ty, a2);
            __syncthreads();
        }
#pragma unroll
        for (int r = 0; r < 4; r++) {
            float4 o = make_float4(fmaxf(a2[r][0] + bfc[4 * tx + 0], 0.0f),
                                   fmaxf(a2[r][1] + bfc[4 * tx + 1], 0.0f),
                                   fmaxf(a2[r][2] + bfc[4 * tx + 2], 0.0f),
                                   fmaxf(a2[r][3] + bfc[4 * tx + 3], 0.0f));
            *(float4*)(g_h0 + (size_t)(b0 + 4 * ty + r) * 128 + 4 * tx) = o;
        }
    }
}

// ---------------- decoder: fp16 mma.sync, B in registers, ldmatrix A ----------------
// act tile: 64 rows x 128 ch fp16, row stride 136 elems (272B).
__device__ __forceinline__ void load_act(const float* src, size_t rowStride,
                                         unsigned char* smp, int HIo, int tid) {
    int m = tid >> 2, f0 = (tid & 3) * 32;
    const float4* s = (const float4*)(src + (size_t)m * rowStride + f0);
#pragma unroll
    for (int i = 0; i < 8; i++) {
        float4 v = s[i];
        int byte = m * 272 + (f0 + 4 * i) * 2;
        *(uint32_t*)(smp + HIo + byte)     = pk2h(__float2half(v.x), __float2half(v.y));
        *(uint32_t*)(smp + HIo + byte + 4) = pk2h(__float2half(v.z), __float2half(v.w));
    }
}

__global__ void __launch_bounds__(256, 1) __cluster_dims__(2, 1, 1)
dec_kernel(const float* __restrict__ z_in, const float* __restrict__ z_tar,
           const float* __restrict__ bihd, const float* __restrict__ bhhd,
           const int* __restrict__ tf_ptr, float* __restrict__ out) {
    extern __shared__ unsigned char smp[];
    const uint32_t SB = (uint32_t)__cvta_generic_to_shared(smp);
    const int tid = threadIdx.x, w = tid >> 5, lane = tid & 31, g = lane >> 2, tq = lane & 3;
    uint32_t rank; asm("mov.u32 %0, %%cluster_ctarank;" : "=r"(rank));
    const int half = (int)rank, pair = blockIdx.x >> 1;
    const int b0 = pair * 64, chb = half * 64;
    const bool tf = (*tf_ptr != 0);
    const int SH[2] = {115712, 133120};

    for (int i = tid; i < 6144; i += 256)
        cp_async16(smp + i * 16, g_Bres[half] + i * 16);
    cp_commit();

    load_act(z_in + ((size_t)b0 * ISEQ + ISEQ - 1) * F_, (size_t)ISEQ * F_, smp, SX, tid);
    load_act(g_h0 + (size_t)b0 * F_, F_, smp, SH[0], tid);

    float hprev[4][2][2];
#pragma unroll
    for (int mt = 0; mt < 4; mt++)
#pragma unroll
        for (int rh = 0; rh < 2; rh++)
#pragma unroll
            for (int e = 0; e < 2; e++)
                hprev[mt][rh][e] = g_h0[(size_t)(b0 + 16 * mt + g + 8 * rh) * 128
                                        + chb + 8 * w + 2 * tq + e];
    float br[2], bz[2], bni[2], bnh[2];
#pragma unroll
    for (int e = 0; e < 2; e++) {
        int ch = chb + 8 * w + 2 * tq + e;
        br[e] = bihd[ch] + bhhd[ch];
        bz[e] = bihd[128 + ch] + bhhd[128 + ch];
        bni[e] = bihd[256 + ch];
        bnh[e] = bhhd[256 + ch];
    }
    const uint32_t swz = (uint32_t)((g & 4) << 2);
    uint32_t bofs[3];
#pragma unroll
    for (int nt = 0; nt < 3; nt++) {
        int col = nt * 64 + 8 * w + g;
        bofs[nt] = (uint32_t)(col * 32) + (((uint32_t)tq * 4) ^ swz);
    }
    // ldmatrix.x4 per-lane address offset: q = lane>>3 selects the 8x8 matrix
    const int q = lane >> 3;
    const uint32_t lm_off = (uint32_t)(((lane & 7) + 8 * (q & 1)) * 272 + (q >> 1) * 16);
    uint32_t pH[2];
#pragma unroll
    for (int st = 0; st < 2; st++) pH[st] = mapa_u32(SB + (uint32_t)SH[st], rank ^ 1);
    cp_wait0();
    __syncthreads();   // B blob resident before register hoist

    // hoist ALL B fragments (time-invariant weights) into registers
    uint32_t Breg[2][8][3][2];
#pragma unroll
    for (int gm = 0; gm < 2; gm++)
#pragma unroll
        for (int kt = 0; kt < 8; kt++)
#pragma unroll
            for (int nt = 0; nt < 3; nt++) {
                uint32_t a0 = SB + (uint32_t)(gm * 49152 + kt * 6144) + bofs[nt];
                Breg[gm][kt][nt][0] = lds32(a0);
                Breg[gm][kt][nt][1] = lds32(a0 ^ 16u);
            }

#pragma unroll 1
    for (int t = 0; t < PSEQ; t++) {
        CSYNC();   // step t-1 writes (own + peer DSMEM) visible; t-1 reads complete
        const int cur = t & 1, nxt = cur ^ 1;
        float C[4][4][4];
#pragma unroll
        for (int a = 0; a < 4; a++)
#pragma unroll
            for (int b = 0; b < 4; b++)
#pragma unroll
                for (int cc = 0; cc < 4; cc++) C[a][b][cc] = 0.0f;
        const bool use_x = (t == 0) || tf;
        const uint32_t xbase = SB + (uint32_t)(use_x ? SX : SH[cur]) + lm_off;
        const uint32_t hbase = SB + (uint32_t)SH[cur] + lm_off;
#pragma unroll
        for (int gm = 0; gm < 2; gm++) {
            const uint32_t ab = (gm == 0) ? xbase : hbase;
#pragma unroll
            for (int kt = 0; kt < 8; kt++) {
                uint32_t af[4][4];
#pragma unroll
                for (int mt = 0; mt < 4; mt++)
                    ldmx4(af[mt], ab + (uint32_t)(mt * 4352 + kt * 32));
#pragma unroll
                for (int nt = 0; nt < 3; nt++) {
                    const int ci = (gm == 0 || nt < 2) ? nt : 3;
#pragma unroll
                    for (int mt = 0; mt < 4; mt++)
                        mma16816(C[ci][mt], af[mt], Breg[gm][kt][nt]);
                }
            }
        }

        // combine -> h stage nxt (own smem + peer DSMEM) + output
#pragma unroll
        for (int mt = 0; mt < 4; mt++)
#pragma unroll
            for (int rh = 0; rh < 2; rh++) {
                const int row = 16 * mt + g + 8 * rh;
                const int ch0 = chb + 8 * w + 2 * tq;
                float hv[2]; __half hh[2];
#pragma unroll
                for (int e = 0; e < 2; e++) {
                    int fi = rh * 2 + e;
                    float rr = sigf(C[0][mt][fi] + br[e]);
                    float zz = sigf(C[1][mt][fi] + bz[e]);
                    float nn = tanhf(C[2][mt][fi] + bni[e] + rr * (C[3][mt][fi] + bnh[e]));
                    float h = (1.0f - zz) * nn + zz * hprev[mt][rh][e];
                    hprev[mt][rh][e] = h;
                    hv[e] = h;
                    hh[e] = __float2half(h);
                }
                const uint32_t byte = (uint32_t)(row * 272 + ch0 * 2);
                uint32_t pk = pk2h(hh[0], hh[1]);
                *(uint32_t*)(smp + SH[nxt] + byte) = pk;
                stc32(pH[nxt] + byte, pk);
                *(float2*)(out + ((size_t)(b0 + row) * PSEQ + t) * F_ + ch0)
                    = make_float2(hv[0], hv[1]);
            }
        __syncthreads();   // all warps done reading X tile before rewrite
        if (tf && (t + 1 < PSEQ))
            load_act(z_tar + ((size_t)b0 * PSEQ + t) * F_, (size_t)PSEQ * F_, smp, SX, tid);
    }
    CSYNC();   // no CTA exits while peer DSMEM stores may be in flight
}

// ---------------- launch ----------------
extern "C" void kernel_launch(void* const* d_in, const int* in_sizes, int n_in,
                              void* d_out, int out_size) {
    const float* z_in  = (const float*)d_in[0];
    const float* z_tar = (const float*)d_in[1];
    const float* Wihe  = (const float*)d_in[2];
    const float* bihe  = (const float*)d_in[4];
    const float* bhhe  = (const float*)d_in[5];
    const float* Wfc   = (const float*)d_in[6];
    const float* bfc   = (const float*)d_in[7];
    const float* Wihd  = (const float*)d_in[8];
    const float* Whhd  = (const float*)d_in[9];
    const float* bihd  = (const float*)d_in[10];
    const float* bhhd  = (const float*)d_in[11];
    const int*   tf    = (const int*)d_in[12];
    float* out = (float*)d_out;

    prep_kernel<<<896, 256>>>(Wihe, Wfc, Wihd, Whhd);

    const int ENC_SMEM = (12288 + 128 * XST + 256 * XST) * 4;
    cudaFuncSetAttribute(enc_kernel, cudaFuncAttributeMaxDynamicSharedMemorySize, ENC_SMEM);
    enc_kernel<<<128, 256, ENC_SMEM>>>(z_in, bihe, bhhe, bfc);

    cudaFuncSetAttribute(dec_kernel, cudaFuncAttributeMaxDynamicSharedMemorySize, SMDEC);
    dec_kernel<<<128, 256, SMDEC>>>(z_in, z_tar, bihd, bhhd, tf, out);
}

// round 16
// speedup vs baseline: 5.1484x; 1.2886x over previous
#include <cuda_runtime.h>
#include <cuda_bf16.h>
#include <cuda_fp16.h>
#include <cstdint>
#include <cstddef>

#define BATCH 4096
#define F_ 128
#define H_ 256
#define ISEQ 96
#define PSEQ 48
#define XST 36
// dec SMEM byte offsets: B blobs (98304) | X | H stage0 | H stage1 (17408 each)
#define SX   98304
#define SMDEC 150528

__device__ float g_WencT[128 * 768];
__device__ float g_WfcT [256 * 128];
__device__ float g_h0   [BATCH * F_];
__device__ __align__(128) unsigned char g_Bres[2][98304]; // Wih_h | Whh_h (fp16) per half

__device__ __forceinline__ float sigf(float x) { return 1.0f / (1.0f + __expf(-x)); }
__device__ __forceinline__ float tanh_fast(float x) {
    float y; asm("tanh.approx.f32 %0, %1;" : "=f"(y) : "f"(x)); return y;
}
__device__ __forceinline__ float sig_fast(float x) {
    return fmaf(tanh_fast(0.5f * x), 0.5f, 0.5f);
}
__device__ __forceinline__ void cp_async16(void* sdst, const void* gsrc) {
    unsigned sa = (unsigned)__cvta_generic_to_shared(sdst);
    asm volatile("cp.async.cg.shared.global [%0], [%1], 16;" :: "r"(sa), "l"(gsrc));
}
__device__ __forceinline__ void cp_commit() { asm volatile("cp.async.commit_group;"); }
__device__ __forceinline__ void cp_wait1()  { asm volatile("cp.async.wait_group 1;"); }
__device__ __forceinline__ void cp_wait0()  { asm volatile("cp.async.wait_group 0;"); }
__device__ __forceinline__ uint32_t lds32(uint32_t a) {
    uint32_t v; asm volatile("ld.shared.b32 %0, [%1];" : "=r"(v) : "r"(a)); return v;
}
__device__ __forceinline__ void ldmx4(uint32_t* r, uint32_t addr) {
    asm volatile("ldmatrix.sync.aligned.m8n8.x4.shared.b16 {%0,%1,%2,%3}, [%4];"
                 : "=r"(r[0]), "=r"(r[1]), "=r"(r[2]), "=r"(r[3]) : "r"(addr));
}
__device__ __forceinline__ void mma16816(float* c, const uint32_t* a, const uint32_t* b) {
    asm volatile("mma.sync.aligned.m16n8k16.row.col.f32.f16.f16.f32 "
                 "{%0,%1,%2,%3},{%4,%5,%6,%7},{%8,%9},{%0,%1,%2,%3};"
                 : "+f"(c[0]), "+f"(c[1]), "+f"(c[2]), "+f"(c[3])
                 : "r"(a[0]), "r"(a[1]), "r"(a[2]), "r"(a[3]), "r"(b[0]), "r"(b[1]));
}
__device__ __forceinline__ uint32_t mapa_u32(uint32_t a, uint32_t r) {
    uint32_t o; asm volatile("mapa.shared::cluster.u32 %0, %1, %2;" : "=r"(o) : "r"(a), "r"(r));
    return o;
}
__device__ __forceinline__ void stc32(uint32_t a, uint32_t v) {
    asm volatile("st.shared::cluster.u32 [%0], %1;" :: "r"(a), "r"(v) : "memory");
}
#define CSYNC() do { asm volatile("barrier.cluster.arrive.aligned;" ::: "memory"); \
                     asm volatile("barrier.cluster.wait.aligned;" ::: "memory"); } while (0)
__device__ __forceinline__ uint32_t pk2h(__half a, __half b) {
    return (uint32_t)__half_as_ushort(a) | ((uint32_t)__half_as_ushort(b) << 16);
}

// ---------------- prep ----------------
__global__ void prep_kernel(const float* __restrict__ Wihe, const float* __restrict__ Wfc,
                            const float* __restrict__ Wihd, const float* __restrict__ Whhd) {
    int idx = blockIdx.x * 256 + threadIdx.x;
    if (idx < 98304) {
        int k = idx / 768, s = idx - k * 768, c = s / 3, g = s - 3 * c;
        g_WencT[idx] = Wihe[(g * 256 + c) * 128 + k];
    } else if (idx < 131072) {
        int j = idx - 98304, k = j / 128, c = j - k * 128;
        g_WfcT[j] = Wfc[c * 256 + k];
    } else if (idx < 229376) {
        int j = idx - 131072;
        int half = j / 49152, r2 = j % 49152, gm = r2 / 24576, e = r2 % 24576;
        int col = e >> 7, k = e & 127;
        int gate = col >> 6, ch = half * 64 + (col & 63);
        const float* W = gm ? Whhd : Wihd;
        float w = W[(size_t)(gate * 128 + ch) * 128 + k];
        int kt = k >> 4, kk = k & 15;
        uint32_t sb = (uint32_t)(kt * 6144 + col * 32) + (uint32_t)((kk * 2) ^ ((col & 4) << 2));
        *(__half*)(g_Bres[half] + gm * 49152 + sb) = __float2half(w);
    }
}

// ---------------- encoder (fp32, proven) ----------------
__device__ __forceinline__ void load_chunk384(float* dst, const float* src, int stride, int tid) {
    int row = tid >> 4, col = (tid & 15) * 24;
    const float* s = src + (size_t)row * stride + col;
    float* d = dst + row * 384 + col;
#pragma unroll
    for (int i = 0; i < 6; i++) cp_async16(d + i * 4, s + i * 4);
}
__device__ __forceinline__ void load_chunk128(float* dst, const float* src, int tid) {
    int row = tid >> 4, col = (tid & 15) * 8;
    cp_async16(dst + row * 128 + col, src + row * 128 + col);
    cp_async16(dst + row * 128 + col + 4, src + row * 128 + col + 4);
}
__device__ __forceinline__ void gemm_x_full(const float* A, const float* Bt,
                                            int tx, int ty, float (&acc)[4][12]) {
#pragma unroll
    for (int k = 0; k < 16; k++) {
        float4 av = *(const float4*)(A + k * XST + 4 * ty);
        const float* bp = Bt + k * 384 + 12 * tx;
        float4 b0 = *(const float4*)bp, b1 = *(const float4*)(bp + 4), b2 = *(const float4*)(bp + 8);
        float aa[4] = {av.x, av.y, av.z, av.w};
        float bb[12] = {b0.x,b0.y,b0.z,b0.w,b1.x,b1.y,b1.z,b1.w,b2.x,b2.y,b2.z,b2.w};
#pragma unroll
        for (int r = 0; r < 4; r++)
#pragma unroll
            for (int j = 0; j < 12; j++) acc[r][j] = fmaf(aa[r], bb[j], acc[r][j]);
    }
}
__device__ __forceinline__ void gemm_fc(const float* A, const float* Bt,
                                        int tx, int ty, float (&acc)[4][4]) {
#pragma unroll
    for (int k = 0; k < 16; k++) {
        float4 av = *(const float4*)(A + k * XST + 4 * ty);
        float4 bv = *(const float4*)(Bt + k * 128 + 4 * tx);
        float aa[4] = {av.x, av.y, av.z, av.w};
        float bb[4] = {bv.x, bv.y, bv.z, bv.w};
#pragma unroll
        for (int r = 0; r < 4; r++)
#pragma unroll
            for (int j = 0; j < 4; j++) acc[r][j] = fmaf(aa[r], bb[j], acc[r][j]);
    }
}

__global__ void __launch_bounds__(256, 1)
enc_kernel(const float* __restrict__ z_in, const float* __restrict__ bihe,
           const float* __restrict__ bhhe, const float* __restrict__ bfc) {
    extern __shared__ float sm[];
    float* Bs = sm;
    float* xs = sm + 12288;
    float* he = xs + 128 * XST;
    const int tid = threadIdx.x, tx = tid & 31, ty = tid >> 5;
    const int b0 = blockIdx.x * 32;
    {
        int m = tid & 31, f0 = (tid >> 5) * 16;
        const float4* s = (const float4*)(z_in + ((size_t)(b0 + m) * ISEQ + ISEQ - 1) * F_ + f0);
        float4 v0 = s[0], v1 = s[1], v2 = s[2], v3 = s[3];
        float vv[16] = {v0.x,v0.y,v0.z,v0.w,v1.x,v1.y,v1.z,v1.w,v2.x,v2.y,v2.z,v2.w,v3.x,v3.y,v3.z,v3.w};
#pragma unroll
        for (int i = 0; i < 16; i++) xs[(f0 + i) * XST + m] = vv[i];
    }
    __syncthreads();
#pragma unroll 1
    for (int cc = 0; cc < 2; cc++) {
        float acc[4][12];
#pragma unroll
        for (int r = 0; r < 4; r++)
#pragma unroll
            for (int j = 0; j < 12; j++) acc[r][j] = 0.0f;
        load_chunk384(Bs, g_WencT + cc * 384, 768, tid);
        cp_commit();
#pragma unroll 1
        for (int ch = 0; ch < 8; ch++) {
            if (ch < 7) {
                load_chunk384(Bs + ((ch + 1) & 1) * 6144,
                              g_WencT + (size_t)(ch + 1) * 16 * 768 + cc * 384, 768, tid);
                cp_commit(); cp_wait1();
            } else cp_wait0();
            __syncthreads();
            gemm_x_full(xs + ch * 16 * XST, Bs + (ch & 1) * 6144, tx, ty, acc);
            __syncthreads();
        }
#pragma unroll
        for (int cj = 0; cj < 4; cj++) {
            int c = cc * 128 + 4 * tx + cj;
            float br = bihe[c] + bhhe[c];
            float bz = bihe[H_ + c] + bhhe[H_ + c];
            float bni = bihe[2 * H_ + c], bnh = bhhe[2 * H_ + c];
#pragma unroll
            for (int r = 0; r < 4; r++) {
                float rr = sigf(acc[r][3 * cj] + br);
                float zz = sigf(acc[r][3 * cj + 1] + bz);
                float nn = tanhf(acc[r][3 * cj + 2] + bni + rr * bnh);
                he[c * XST + 4 * ty + r] = (1.0f - zz) * nn;
            }
        }
    }
    {
        float a2[4][4];
#pragma unroll
        for (int r = 0; r < 4; r++)
#pragma unroll
            for (int j = 0; j < 4; j++) a2[r][j] = 0.0f;
        load_chunk128(Bs, g_WfcT, tid);
        cp_commit();
#pragma unroll 1
        for (int ch = 0; ch < 16; ch++) {
            if (ch < 15) {
                load_chunk128(Bs + ((ch + 1) & 1) * 6144, g_WfcT + (ch + 1) * 16 * 128, tid);
                cp_commit(); cp_wait1();
            } else cp_wait0();
            __syncthreads();
            gemm_fc(he + ch * 16 * XST, Bs + (ch & 1) * 6144, tx, ty, a2);
            __syncthreads();
        }
#pragma unroll
        for (int r = 0; r < 4; r++) {
            float4 o = make_float4(fmaxf(a2[r][0] + bfc[4 * tx + 0], 0.0f),
                                   fmaxf(a2[r][1] + bfc[4 * tx + 1], 0.0f),
                                   fmaxf(a2[r][2] + bfc[4 * tx + 2], 0.0f),
                                   fmaxf(a2[r][3] + bfc[4 * tx + 3], 0.0f));
            *(float4*)(g_h0 + (size_t)(b0 + 4 * ty + r) * 128 + 4 * tx) = o;
        }
    }
}

// ---------------- decoder: fp16 mma.sync, B in registers, ldmatrix A ----------------
// act tile: 64 rows x 128 ch fp16, row stride 136 elems (272B).
__device__ __forceinline__ void load_act(const float* src, size_t rowStride,
                                         unsigned char* smp, int HIo, int tid) {
    int m = tid >> 2, f0 = (tid & 3) * 32;
    const float4* s = (const float4*)(src + (size_t)m * rowStride + f0);
#pragma unroll
    for (int i = 0; i < 8; i++) {
        float4 v = s[i];
        int byte = m * 272 + (f0 + 4 * i) * 2;
        *(uint32_t*)(smp + HIo + byte)     = pk2h(__float2half(v.x), __float2half(v.y));
        *(uint32_t*)(smp + HIo + byte + 4) = pk2h(__float2half(v.z), __float2half(v.w));
    }
}

__global__ void __launch_bounds__(256, 1) __cluster_dims__(2, 1, 1)
dec_kernel(const float* __restrict__ z_in, const float* __restrict__ z_tar,
           const float* __restrict__ bihd, const float* __restrict__ bhhd,
           const int* __restrict__ tf_ptr, float* __restrict__ out) {
    extern __shared__ unsigned char smp[];
    const uint32_t SB = (uint32_t)__cvta_generic_to_shared(smp);
    const int tid = threadIdx.x, w = tid >> 5, lane = tid & 31, g = lane >> 2, tq = lane & 3;
    uint32_t rank; asm("mov.u32 %0, %%cluster_ctarank;" : "=r"(rank));
    const int half = (int)rank, pair = blockIdx.x >> 1;
    const int b0 = pair * 64, chb = half * 64;
    const bool tf = (*tf_ptr != 0);
    const int SH[2] = {115712, 133120};

    for (int i = tid; i < 6144; i += 256)
        cp_async16(smp + i * 16, g_Bres[half] + i * 16);
    cp_commit();

    load_act(z_in + ((size_t)b0 * ISEQ + ISEQ - 1) * F_, (size_t)ISEQ * F_, smp, SX, tid);
    load_act(g_h0 + (size_t)b0 * F_, F_, smp, SH[0], tid);

    float hprev[4][2][2];
#pragma unroll
    for (int mt = 0; mt < 4; mt++)
#pragma unroll
        for (int rh = 0; rh < 2; rh++)
#pragma unroll
            for (int e = 0; e < 2; e++)
                hprev[mt][rh][e] = g_h0[(size_t)(b0 + 16 * mt + g + 8 * rh) * 128
                                        + chb + 8 * w + 2 * tq + e];
    float br[2], bz[2], bni[2], bnh[2];
#pragma unroll
    for (int e = 0; e < 2; e++) {
        int ch = chb + 8 * w + 2 * tq + e;
        br[e] = bihd[ch] + bhhd[ch];
        bz[e] = bihd[128 + ch] + bhhd[128 + ch];
        bni[e] = bihd[256 + ch];
        bnh[e] = bhhd[256 + ch];
    }
    const uint32_t swz = (uint32_t)((g & 4) << 2);
    uint32_t bofs[3];
#pragma unroll
    for (int nt = 0; nt < 3; nt++) {
        int col = nt * 64 + 8 * w + g;
        bofs[nt] = (uint32_t)(col * 32) + (((uint32_t)tq * 4) ^ swz);
    }
    // ldmatrix.x4 per-lane address offset: q = lane>>3 selects the 8x8 matrix
    const int q = lane >> 3;
    const uint32_t lm_off = (uint32_t)(((lane & 7) + 8 * (q & 1)) * 272 + (q >> 1) * 16);
    uint32_t pH[2];
#pragma unroll
    for (int st = 0; st < 2; st++) pH[st] = mapa_u32(SB + (uint32_t)SH[st], rank ^ 1);
    cp_wait0();
    __syncthreads();   // B blob resident before register hoist

    // hoist ALL B fragments (time-invariant weights) into registers
    uint32_t Breg[2][8][3][2];
#pragma unroll
    for (int gm = 0; gm < 2; gm++)
#pragma unroll
        for (int kt = 0; kt < 8; kt++)
#pragma unroll
            for (int nt = 0; nt < 3; nt++) {
                uint32_t a0 = SB + (uint32_t)(gm * 49152 + kt * 6144) + bofs[nt];
                Breg[gm][kt][nt][0] = lds32(a0);
                Breg[gm][kt][nt][1] = lds32(a0 ^ 16u);
            }

#pragma unroll 1
    for (int t = 0; t < PSEQ; t++) {
        CSYNC();   // step t-1 writes (own + peer DSMEM) visible; t-1 reads complete
        const int cur = t & 1, nxt = cur ^ 1;
        float C[4][4][4];
#pragma unroll
        for (int a = 0; a < 4; a++)
#pragma unroll
            for (int b = 0; b < 4; b++)
#pragma unroll
                for (int cc = 0; cc < 4; cc++) C[a][b][cc] = 0.0f;
        const bool use_x = (t == 0) || tf;
        const uint32_t xbase = SB + (uint32_t)(use_x ? SX : SH[cur]) + lm_off;
        const uint32_t hbase = SB + (uint32_t)SH[cur] + lm_off;
#pragma unroll
        for (int gm = 0; gm < 2; gm++) {
            const uint32_t ab = (gm == 0) ? xbase : hbase;
#pragma unroll
            for (int kt = 0; kt < 8; kt++) {
                uint32_t af[4][4];
#pragma unroll
                for (int mt = 0; mt < 4; mt++)
                    ldmx4(af[mt], ab + (uint32_t)(mt * 4352 + kt * 32));
#pragma unroll
                for (int nt = 0; nt < 3; nt++) {
                    const int ci = (gm == 0 || nt < 2) ? nt : 3;
#pragma unroll
                    for (int mt = 0; mt < 4; mt++)
                        mma16816(C[ci][mt], af[mt], Breg[gm][kt][nt]);
                }
            }
        }

        // combine -> h stage nxt (own smem + peer DSMEM) + output
#pragma unroll
        for (int mt = 0; mt < 4; mt++)
#pragma unroll
            for (int rh = 0; rh < 2; rh++) {
                const int row = 16 * mt + g + 8 * rh;
                const int ch0 = chb + 8 * w + 2 * tq;
                float hv[2]; __half hh[2];
#pragma unroll
                for (int e = 0; e < 2; e++) {
                    int fi = rh * 2 + e;
                    float rr = sig_fast(C[0][mt][fi] + br[e]);
                    float zz = sig_fast(C[1][mt][fi] + bz[e]);
                    float nn = tanh_fast(C[2][mt][fi] + bni[e] + rr * (C[3][mt][fi] + bnh[e]));
                    float h = (1.0f - zz) * nn + zz * hprev[mt][rh][e];
                    hprev[mt][rh][e] = h;
                    hv[e] = h;
                    hh[e] = __float2half(h);
                }
                const uint32_t byte = (uint32_t)(row * 272 + ch0 * 2);
                uint32_t pk = pk2h(hh[0], hh[1]);
                *(uint32_t*)(smp + SH[nxt] + byte) = pk;
                stc32(pH[nxt] + byte, pk);
                *(float2*)(out + ((size_t)(b0 + row) * PSEQ + t) * F_ + ch0)
                    = make_float2(hv[0], hv[1]);
            }
        __syncthreads();   // all warps done reading X tile before rewrite
        if (tf && (t + 1 < PSEQ))
            load_act(z_tar + ((size_t)b0 * PSEQ + t) * F_, (size_t)PSEQ * F_, smp, SX, tid);
    }
    CSYNC();   // no CTA exits while peer DSMEM stores may be in flight
}

// ---------------- launch ----------------
extern "C" void kernel_launch(void* const* d_in, const int* in_sizes, int n_in,
                              void* d_out, int out_size) {
    const float* z_in  = (const float*)d_in[0];
    const float* z_tar = (const float*)d_in[1];
    const float* Wihe  = (const float*)d_in[2];
    const float* bihe  = (const float*)d_in[4];
    const float* bhhe  = (const float*)d_in[5];
    const float* Wfc   = (const float*)d_in[6];
    const float* bfc   = (const float*)d_in[7];
    const float* Wihd  = (const float*)d_in[8];
    const float* Whhd  = (const float*)d_in[9];
    const float* bihd  = (const float*)d_in[10];
    const float* bhhd  = (const float*)d_in[11];
    const int*   tf    = (const int*)d_in[12];
    float* out = (float*)d_out;

    prep_kernel<<<896, 256>>>(Wihe, Wfc, Wihd, Whhd);

    const int ENC_SMEM = (12288 + 128 * XST + 256 * XST) * 4;
    cudaFuncSetAttribute(enc_kernel, cudaFuncAttributeMaxDynamicSharedMemorySize, ENC_SMEM);
    enc_kernel<<<128, 256, ENC_SMEM>>>(z_in, bihe, bhhe, bfc);

    cudaFuncSetAttribute(dec_kernel, cudaFuncAttributeMaxDynamicSharedMemorySize, SMDEC);
    dec_kernel<<<128, 256, SMDEC>>>(z_in, z_tar, bihd, bhhd, tf, out);
}